// round 13
// baseline (speedup 1.0000x reference)
#include <cuda_runtime.h>
#include <cuda_bf16.h>
#include <cuda_fp16.h>
#include <cooperative_groups.h>
#include <math.h>
#include <stdint.h>

namespace cg = cooperative_groups;

#define T_STEPS 100
#define BATCH   256
#define IN_DIM  784
#define HID     1024
#define OUTD    10
#define P_DIM   64
#define ALPHA   0.05f   // DT / TAUM

#define M_TOT   (T_STEPS * BATCH)   // 25600
#define K_PAD   832                 // 13 * 64 fp16 (128B rows)
#define N_CHUNK 13
#define TILES_PER_T 16

#define NCTAS_LOOP 64
#define NCTAS_GEMM 1600
#define NCTAS_ALL  (NCTAS_LOOP + NCTAS_GEMM)

#define PREP_WIN_BLKS 416           // HID*104/256
#define PREP_SPK_BLKS 10400         // M_TOT*104/256
#define PREP_BLKS     (PREP_WIN_BLKS + PREP_SPK_BLKS)

// ---------------- scratch (static device globals) ----------------
__device__ __half g_Iin[(size_t)T_STEPS * BATCH * HID];   // fp16 input currents
__device__ float  g_logits[BATCH * OUTD];
__device__ __half g_spkh[(size_t)M_TOT * K_PAD];
__device__ __half g_WinH[(size_t)HID * K_PAD];
__device__ unsigned int g_tdone[T_STEPS];

// ---------------- helpers ----------------
__device__ __forceinline__ uint32_t smem_u32(const void* p) {
    uint32_t a;
    asm("{ .reg .u64 t; cvta.to.shared.u64 t, %1; cvt.u32.u64 %0, t; }" : "=r"(a) : "l"(p));
    return a;
}
#define SWZ128(o) ((o) ^ (((o) >> 3) & 0x70))
#define CP_COMMIT() asm volatile("cp.async.commit_group;" ::: "memory")
#define CP_WAIT(n)  asm volatile("cp.async.wait_group %0;" :: "n"(n) : "memory")

__device__ __forceinline__ void ldm_x4(uint32_t* r, uint32_t addr) {
    asm volatile("ldmatrix.sync.aligned.m8n8.x4.shared.b16 {%0,%1,%2,%3}, [%4];"
                 : "=r"(r[0]), "=r"(r[1]), "=r"(r[2]), "=r"(r[3]) : "r"(addr));
}
__device__ __forceinline__ void mma_bf16(float* c, const uint32_t* a, uint32_t b0, uint32_t b1) {
    asm volatile("mma.sync.aligned.m16n8k16.row.col.f32.bf16.bf16.f32 "
                 "{%0,%1,%2,%3}, {%4,%5,%6,%7}, {%8,%9}, {%0,%1,%2,%3};"
                 : "+f"(c[0]), "+f"(c[1]), "+f"(c[2]), "+f"(c[3])
                 : "r"(a[0]), "r"(a[1]), "r"(a[2]), "r"(a[3]), "r"(b0), "r"(b1));
}
__device__ __forceinline__ void mma_f16(float* c, const uint32_t* a, uint32_t b0, uint32_t b1) {
    asm volatile("mma.sync.aligned.m16n8k16.row.col.f32.f16.f16.f32 "
                 "{%0,%1,%2,%3}, {%4,%5,%6,%7}, {%8,%9}, {%0,%1,%2,%3};"
                 : "+f"(c[0]), "+f"(c[1]), "+f"(c[2]), "+f"(c[3])
                 : "r"(a[0]), "r"(a[1]), "r"(a[2]), "r"(a[3]), "r"(b0), "r"(b1));
}
#define MBARRIER_INIT(a, c) \
    asm volatile("mbarrier.init.shared.b64 [%0], %1;" :: "r"(a), "r"(c) : "memory")
// release-arrive on peer rank's mbarrier at the same smem offset
__device__ __forceinline__ void mbar_arrive_peer(uint32_t localAddr, uint32_t rk) {
    asm volatile("{\n\t.reg .b32 ra;\n\t"
                 "mapa.shared::cluster.u32 ra, %0, %1;\n\t"
                 "mbarrier.arrive.release.cluster.shared::cluster.b64 _, [ra];\n\t}"
                 :: "r"(localAddr), "r"(rk) : "memory");
}
#define MBAR_WAIT_CL(a, ph) do {                                                        \
    uint32_t _m = (a), _p = (ph), _d;                                                   \
    asm volatile("{\n\t.reg .pred p;\n\t"                                               \
        "mbarrier.try_wait.parity.acquire.cluster.shared::cta.b64 p, [%1], %2;\n\t"     \
        "selp.b32 %0, 1, 0, p;\n\t}" : "=r"(_d) : "r"(_m), "r"(_p) : "memory");         \
    if (!_d) {                                                                          \
        asm volatile("{\n\t.reg .pred P1;\n\tWLC%=:\n\t"                                \
            "mbarrier.try_wait.parity.acquire.cluster.shared::cta.b64 P1, [%0], %1, 0x989680;\n\t" \
            "@P1 bra.uni WDC%=;\n\tbra.uni WLC%=;\n\tWDC%=:\n\t}"                       \
            :: "r"(_m), "r"(_p) : "memory");                                            \
    }                                                                                   \
} while (0)

// ---------------- merged prep kernel ----------------
__global__ void prep_kernel(const float* __restrict__ spk, const float* __restrict__ Win) {
    const int blk = blockIdx.x;
    const int tid = threadIdx.x;
    if (blk == 0 && tid < T_STEPS) g_tdone[tid] = 0u;
    if (blk < 10 && blk * 256 + tid < BATCH * OUTD) g_logits[blk * 256 + tid] = 0.0f;

    if (blk < PREP_WIN_BLKS) {
        int i   = blk * 256 + tid;                 // < HID*104
        int row = i / (K_PAD / 8);
        int c0  = (i % (K_PAD / 8)) * 8;
        __half v[8];
        if (c0 < IN_DIM) {
            const float4* src = (const float4*)&Win[(size_t)row * IN_DIM + c0];
            float4 f0 = src[0], f1 = src[1];
            v[0] = __float2half_rn(f0.x); v[1] = __float2half_rn(f0.y);
            v[2] = __float2half_rn(f0.z); v[3] = __float2half_rn(f0.w);
            v[4] = __float2half_rn(f1.x); v[5] = __float2half_rn(f1.y);
            v[6] = __float2half_rn(f1.z); v[7] = __float2half_rn(f1.w);
        } else {
            #pragma unroll
            for (int j = 0; j < 8; j++) v[j] = __float2half_rn(0.0f);
        }
        *(uint4*)&g_WinH[(size_t)row * K_PAD + c0] = *(uint4*)v;
    } else {
        int i   = (blk - PREP_WIN_BLKS) * 256 + tid;   // < M_TOT*104
        int row = i / (K_PAD / 8);
        int c0  = (i % (K_PAD / 8)) * 8;
        __half v[8];
        if (c0 < IN_DIM) {
            const float4* src = (const float4*)&spk[(size_t)row * IN_DIM + c0];
            float4 f0 = src[0], f1 = src[1];
            v[0] = __float2half_rn(f0.x); v[1] = __float2half_rn(f0.y);
            v[2] = __float2half_rn(f0.z); v[3] = __float2half_rn(f0.w);
            v[4] = __float2half_rn(f1.x); v[5] = __float2half_rn(f1.y);
            v[6] = __float2half_rn(f1.z); v[7] = __float2half_rn(f1.w);
        } else {
            #pragma unroll
            for (int j = 0; j < 8; j++) v[j] = __float2half_rn(0.0f);
        }
        *(uint4*)&g_spkh[(size_t)row * K_PAD + c0] = *(uint4*)v;
    }
}

// ---------------- gemm role (fp16, fp16 Iin epilogue) ----------------
#define TILE_BYTES  16384
#define STAGE_BYTES (2 * TILE_BYTES)
#define GEMM_SMEM   (2 * STAGE_BYTES)   // 65536

__device__ __forceinline__ void copy_tile(uint32_t sdst, const __half* __restrict__ g,
                                          int row0, int k0, int tid) {
    #pragma unroll
    for (int j = 0; j < 4; j++) {
        int i   = tid + j * 256;
        int row = i >> 3;
        int cb  = i & 7;
        const void* gp = g + (size_t)(row0 + row) * K_PAD + k0 + cb * 8;
        uint32_t so = sdst + SWZ128(row * 128 + cb * 16);
        asm volatile("cp.async.cg.shared.global [%0], [%1], 16;" :: "r"(so), "l"(gp));
    }
}

__device__ void gemm_role(char* smraw, int gid) {
    const uint32_t sb  = smem_u32(smraw);
    const int tid  = threadIdx.x;
    const int wid  = tid >> 5;
    const int lane = tid & 31;
    const int m0 = (gid >> 3) * 128;
    const int n0 = (gid & 7) * 128;
    const int wm = (wid & 3) * 32;
    const int wn = (wid >> 2) * 64;

    const uint32_t stA[2] = {sb,                  sb + STAGE_BYTES};
    const uint32_t stB[2] = {stA[0] + TILE_BYTES, stA[1] + TILE_BYTES};

    float acc[2][8][4];
    #pragma unroll
    for (int mi = 0; mi < 2; mi++)
        #pragma unroll
        for (int nj = 0; nj < 8; nj++)
            #pragma unroll
            for (int q = 0; q < 4; q++) acc[mi][nj][q] = 0.0f;

    copy_tile(stA[0], g_spkh, m0, 0, tid);
    copy_tile(stB[0], g_WinH, n0, 0, tid);
    CP_COMMIT();
    copy_tile(stA[1], g_spkh, m0, 64, tid);
    copy_tile(stB[1], g_WinH, n0, 64, tid);
    CP_COMMIT();

    const int arow = wm + (lane & 15);
    const int acolL = (lane >> 4) << 4;
    const int brow = (lane & 7) + ((lane >> 4) << 3);
    const int bcolL = ((lane >> 3) & 1) << 4;

    for (int k = 0; k < N_CHUNK; k++) {
        const int s = k & 1;
        if (k < N_CHUNK - 1) CP_WAIT(1); else CP_WAIT(0);
        __syncthreads();

        #pragma unroll
        for (int ks = 0; ks < 4; ks++) {
            const int kb = ks * 32;
            uint32_t af[2][4];
            ldm_x4(af[0], stA[s] + SWZ128((arow)      * 128 + kb + acolL));
            ldm_x4(af[1], stA[s] + SWZ128((arow + 16) * 128 + kb + acolL));

            #pragma unroll
            for (int nb = 0; nb < 4; nb++) {
                const uint32_t boff = SWZ128((wn + nb * 16 + brow) * 128 + kb + bcolL);
                uint32_t bh[4];
                ldm_x4(bh, stB[s] + boff);
                #pragma unroll
                for (int mi = 0; mi < 2; mi++) {
                    mma_f16(acc[mi][nb * 2 + 0], af[mi], bh[0], bh[1]);
                    mma_f16(acc[mi][nb * 2 + 1], af[mi], bh[2], bh[3]);
                }
            }
        }
        __syncthreads();

        if (k + 2 < N_CHUNK) {
            const int k0 = (k + 2) * 64;
            copy_tile(stA[s], g_spkh, m0, k0, tid);
            copy_tile(stB[s], g_WinH, n0, k0, tid);
            CP_COMMIT();
        }
    }

    const int r0 = lane >> 2;
    const int c0 = (lane & 3) * 2;
    #pragma unroll
    for (int mi = 0; mi < 2; mi++) {
        #pragma unroll
        for (int nj = 0; nj < 8; nj++) {
            const int row = m0 + wm + mi * 16 + r0;
            const int col = n0 + wn + nj * 8 + c0;
            __half2 v01 = __floats2half2_rn(acc[mi][nj][0], acc[mi][nj][1]);
            __half2 v23 = __floats2half2_rn(acc[mi][nj][2], acc[mi][nj][3]);
            *(__half2*)&g_Iin[(size_t)row * HID + col]       = v01;
            *(__half2*)&g_Iin[(size_t)(row + 8) * HID + col] = v23;
        }
    }

    __syncthreads();
    if (tid == 0) {
        __threadfence();
        atomicAdd(&g_tdone[gid >> 4], 1u);
    }
}

// ---------------- loop role: mbarrier exchange + fused readout partials ----------------
#define CLUSTER_N   4
#define ROWS_PER_CL 16
#define H_PER_CTA   256

#define L_OFF_POUT  0        // 32KB
#define L_OFF_WPL   32768    // 32KB
#define L_OFF_TH    65536    // 8KB
#define L_OFF_U     73728    // 2KB
#define L_OFF_UPART 75776    // 8KB (also reused as wred at end)
#define L_OFF_MBOX  83968    // 16KB
#define L_OFF_MBAR  100352   // 8B mbarrier (pad to 128)
#define LOOP_SMEM   100480

#define FUSED_SMEM  (LOOP_SMEM > GEMM_SMEM ? LOOP_SMEM : GEMM_SMEM)

__device__ void loop_role(char* smraw, int bid,
                          const float* __restrict__ pin, const float* __restrict__ pout,
                          const float* __restrict__ l, const float* __restrict__ Wout) {
    const uint32_t sb = smem_u32(smraw);

    cg::cluster_group cl = cg::this_cluster();
    const int rank = cl.block_rank();
    const int cidx = bid / CLUSTER_N;
    const int b0   = cidx * ROWS_PER_CL;
    const int H0   = rank * H_PER_CTA;
    const int tid  = threadIdx.x;
    const int wid  = tid >> 5;
    const int lane = tid & 31;

    for (int i = tid; i < H_PER_CTA * P_DIM; i += 256) {
        int hl = i >> 6;
        int p  = i & 63;
        float pv = pout[(size_t)(H0 + hl) * P_DIM + p];
        *(__nv_bfloat16*)(smraw + L_OFF_POUT + (hl >> 6) * 8192
                          + SWZ128(p * 128 + (hl & 63) * 2)) = __float2bfloat16(pv);
        float wv = pin[(size_t)(H0 + hl) * P_DIM + p] * l[p];
        *(__nv_bfloat16*)(smraw + L_OFF_WPL + SWZ128(hl * 128 + p * 2)) = __float2bfloat16(wv);
    }
    for (int i = tid; i < (8192 + 2048) / 4; i += 256)
        ((uint32_t*)(smraw + L_OFF_TH))[i] = 0;
    if (tid == 0) MBARRIER_INIT(sb + L_OFF_MBAR, 4 * 256);   // 4 ranks x 256 threads per phase

    const int kg   = wid >> 2;
    const int wn16 = (wid & 3) * 16;
    const int aRow = lane & 15;
    const int aCol = (lane >> 4) << 4;
    const int bRow = (lane & 7) + ((lane >> 4) << 3);
    const int bCol = ((lane >> 3) & 1) << 4;
    const int r    = lane >> 2;
    const int c2   = (lane & 3) * 2;

    const int r_e  = tid >> 4;
    const int pe   = (tid & 15) * 4;
    char* mboxLocal = smraw + L_OFF_MBOX;
    char* peerMb[CLUSTER_N];
    #pragma unroll
    for (int rk = 0; rk < CLUSTER_N; rk++)
        peerMb[rk] = (char*)cl.map_shared_rank((void*)mboxLocal, rk);

    float2 memv[8], rmv[8];
    #pragma unroll
    for (int j = 0; j < 8; j++) { memv[j] = make_float2(0.f, 0.f); rmv[j] = make_float2(-2.f, -2.f); }

    cl.sync();   // weights + mbarrier init visible cluster-wide

    for (int t = 0; t < T_STEPS; t++) {
        if (tid == 0) {
            volatile unsigned int* f = &g_tdone[t];
            while (*f < TILES_PER_T) {}
            __threadfence();
        }
        __syncthreads();
        const int buf = t & 1;

        float2 iin[8];
        {
            const size_t base = ((size_t)t * BATCH + b0 + r) * HID + H0 + wid * 32 + c2;
            #pragma unroll
            for (int nb = 0; nb < 2; nb++)
                #pragma unroll
                for (int sub = 0; sub < 2; sub++) {
                    uint32_t w0 = __ldcs((const uint32_t*)&g_Iin[base + nb * 16 + sub * 8]);
                    uint32_t w1 = __ldcs((const uint32_t*)&g_Iin[base + 8 * HID + nb * 16 + sub * 8]);
                    iin[nb * 2 + sub]     = __half22float2(*(__half2*)&w0);
                    iin[4 + nb * 2 + sub] = __half22float2(*(__half2*)&w1);
                }
        }

        // ---- phase A: partial U[16r x 16p] over h-half kg ----
        float accA[2][4] = {{0.f,0.f,0.f,0.f},{0.f,0.f,0.f,0.f}};
        #pragma unroll
        for (int cc = 0; cc < 2; cc++) {
            const int ch = kg * 2 + cc;
            const uint32_t thB = sb + L_OFF_TH + ch * 2048;
            const uint32_t poB = sb + L_OFF_POUT + ch * 8192;
            #pragma unroll
            for (int ks = 0; ks < 4; ks++) {
                const int kb = ks * 32;
                uint32_t af[4], bf[4];
                ldm_x4(af, thB + SWZ128(aRow * 128 + kb + aCol));
                ldm_x4(bf, poB + SWZ128((wn16 + bRow) * 128 + kb + bCol));
                mma_bf16(accA[0], af, bf[0], bf[1]);
                mma_bf16(accA[1], af, bf[2], bf[3]);
            }
        }
        {
            float* up = (float*)(smraw + L_OFF_UPART);
            const int rowA = (kg * 16 + r) * 64 + wn16;
            const int rowB = (kg * 16 + r + 8) * 64 + wn16;
            *(float2*)&up[rowA + 0 + c2] = make_float2(accA[0][0], accA[0][1]);
            *(float2*)&up[rowA + 8 + c2] = make_float2(accA[1][0], accA[1][1]);
            *(float2*)&up[rowB + 0 + c2] = make_float2(accA[0][2], accA[0][3]);
            *(float2*)&up[rowB + 8 + c2] = make_float2(accA[1][2], accA[1][3]);
        }
        __syncthreads();

        // pair-sum kg halves, pack bf16, scatter to all ranks, release-arrive
        {
            const float* up = (const float*)(smraw + L_OFF_UPART);
            float v0 = up[r_e * 64 + pe + 0] + up[(16 + r_e) * 64 + pe + 0];
            float v1 = up[r_e * 64 + pe + 1] + up[(16 + r_e) * 64 + pe + 1];
            float v2 = up[r_e * 64 + pe + 2] + up[(16 + r_e) * 64 + pe + 2];
            float v3 = up[r_e * 64 + pe + 3] + up[(16 + r_e) * 64 + pe + 3];
            uint2 pk;
            __nv_bfloat162 b01 = __floats2bfloat162_rn(v0, v1);
            __nv_bfloat162 b23 = __floats2bfloat162_rn(v2, v3);
            pk.x = *(uint32_t*)&b01;
            pk.y = *(uint32_t*)&b23;
            const int moff = ((buf * CLUSTER_N + rank) * 16 + r_e) * 128 + pe * 2;
            #pragma unroll
            for (int rk = 0; rk < CLUSTER_N; rk++)
                *(uint2*)(peerMb[rk] + moff) = pk;
            #pragma unroll
            for (int rk = 0; rk < CLUSTER_N; rk++)
                mbar_arrive_peer(sb + L_OFF_MBAR, (uint32_t)rk);
        }
        MBAR_WAIT_CL(sb + L_OFF_MBAR, t & 1);

        {
            float s0 = 0.f, s1 = 0.f, s2 = 0.f, s3 = 0.f;
            #pragma unroll
            for (int rk = 0; rk < CLUSTER_N; rk++) {
                uint2 q = *(uint2*)(mboxLocal + ((buf * CLUSTER_N + rk) * 16 + r_e) * 128 + pe * 2);
                float2 f01 = __bfloat1622float2(*(__nv_bfloat162*)&q.x);
                float2 f23 = __bfloat1622float2(*(__nv_bfloat162*)&q.y);
                s0 += f01.x; s1 += f01.y; s2 += f23.x; s3 += f23.y;
            }
            uint2 pk;
            __nv_bfloat162 b01 = __floats2bfloat162_rn(s0, s1);
            __nv_bfloat162 b23 = __floats2bfloat162_rn(s2, s3);
            pk.x = *(uint32_t*)&b01;
            pk.y = *(uint32_t*)&b23;
            *(uint2*)(smraw + L_OFF_U + SWZ128(r_e * 128 + pe * 2)) = pk;
        }
        __syncthreads();

        // ---- phase B ----
        float accB[2][2][4];
        #pragma unroll
        for (int nb = 0; nb < 2; nb++)
            #pragma unroll
            for (int sub = 0; sub < 2; sub++)
                #pragma unroll
                for (int q = 0; q < 4; q++) accB[nb][sub][q] = 0.f;

        const uint32_t uB = sb + L_OFF_U;
        const uint32_t wB = sb + L_OFF_WPL;
        #pragma unroll
        for (int ks = 0; ks < 4; ks++) {
            const int kb = ks * 32;
            uint32_t af[4];
            ldm_x4(af, uB + SWZ128(aRow * 128 + kb + aCol));
            #pragma unroll
            for (int nb = 0; nb < 2; nb++) {
                uint32_t bf[4];
                ldm_x4(bf, wB + SWZ128((wid * 32 + nb * 16 + bRow) * 128 + kb + bCol));
                mma_bf16(accB[nb][0], af, bf[0], bf[1]);
                mma_bf16(accB[nb][1], af, bf[2], bf[3]);
            }
        }

        #pragma unroll
        for (int nb = 0; nb < 2; nb++) {
            #pragma unroll
            for (int sub = 0; sub < 2; sub++) {
                const int j  = nb * 2 + sub;
                const int hc = wid * 32 + nb * 16 + sub * 8 + c2;
                const uint32_t thBase = (uint32_t)(L_OFF_TH + (hc >> 6) * 2048);
                {
                    float m0 = (iin[j].x + accB[nb][sub][0] - memv[j].x) * ALPHA;
                    float m1 = (iin[j].y + accB[nb][sub][1] - memv[j].y) * ALPHA;
                    memv[j].x = m0;  memv[j].y = m1;
                    float tv0 = tanhf(m0), tv1 = tanhf(m1);
                    rmv[j].x = fmaxf(rmv[j].x, tv0);
                    rmv[j].y = fmaxf(rmv[j].y, tv1);
                    *(__nv_bfloat162*)(smraw + thBase + SWZ128(r * 128 + (hc & 63) * 2)) =
                        __floats2bfloat162_rn(tv0, tv1);
                }
                {
                    float m0 = (iin[4 + j].x + accB[nb][sub][2] - memv[4 + j].x) * ALPHA;
                    float m1 = (iin[4 + j].y + accB[nb][sub][3] - memv[4 + j].y) * ALPHA;
                    memv[4 + j].x = m0;  memv[4 + j].y = m1;
                    float tv0 = tanhf(m0), tv1 = tanhf(m1);
                    rmv[4 + j].x = fmaxf(rmv[4 + j].x, tv0);
                    rmv[4 + j].y = fmaxf(rmv[4 + j].y, tv1);
                    *(__nv_bfloat162*)(smraw + thBase + SWZ128((r + 8) * 128 + (hc & 63) * 2)) =
                        __floats2bfloat162_rn(tv0, tv1);
                }
            }
        }
    }

    // ---- fused readout partials: logits[b][o] += sum_h rm[b][h] * Wout[o][h] ----
    float pr0[OUTD], pr1[OUTD];
    #pragma unroll
    for (int o = 0; o < OUTD; o++) { pr0[o] = 0.f; pr1[o] = 0.f; }
    #pragma unroll
    for (int nb = 0; nb < 2; nb++)
        #pragma unroll
        for (int sub = 0; sub < 2; sub++) {
            const int j  = nb * 2 + sub;
            const int hc = wid * 32 + nb * 16 + sub * 8 + c2;
            #pragma unroll
            for (int o = 0; o < OUTD; o++) {
                float2 wv = *(const float2*)&Wout[(size_t)o * HID + H0 + hc];
                pr0[o] = fmaf(rmv[j].x,     wv.x, fmaf(rmv[j].y,     wv.y, pr0[o]));
                pr1[o] = fmaf(rmv[4 + j].x, wv.x, fmaf(rmv[4 + j].y, wv.y, pr1[o]));
            }
        }
    #pragma unroll
    for (int o = 0; o < OUTD; o++) {
        pr0[o] += __shfl_xor_sync(0xffffffffu, pr0[o], 1);
        pr0[o] += __shfl_xor_sync(0xffffffffu, pr0[o], 2);
        pr1[o] += __shfl_xor_sync(0xffffffffu, pr1[o], 1);
        pr1[o] += __shfl_xor_sync(0xffffffffu, pr1[o], 2);
    }
    __syncthreads();   // UPART reads done; reuse as wred[8][16][12]
    float* wred = (float*)(smraw + L_OFF_UPART);
    if ((lane & 3) == 0) {
        #pragma unroll
        for (int o = 0; o < OUTD; o++) {
            wred[(wid * 16 + r)     * 12 + o] = pr0[o];
            wred[(wid * 16 + r + 8) * 12 + o] = pr1[o];
        }
    }
    __syncthreads();
    if (tid < ROWS_PER_CL * OUTD) {
        int row = tid / OUTD;
        int o   = tid % OUTD;
        float s = 0.f;
        #pragma unroll
        for (int w = 0; w < 8; w++) s += wred[(w * 16 + row) * 12 + o];
        atomicAdd(&g_logits[(b0 + row) * OUTD + o], s);
    }
    cl.sync();   // no CTA exits while peer DSMEM traffic could be in flight
}

// ---------------- fused heterogeneous kernel ----------------
__global__ void __cluster_dims__(CLUSTER_N, 1, 1) __launch_bounds__(256, 2)
fused_kernel(const float* __restrict__ pin, const float* __restrict__ pout,
             const float* __restrict__ l, const float* __restrict__ Wout) {
    extern __shared__ char smraw[];
    const int bid = blockIdx.x;
    if (bid < NCTAS_LOOP) {
        loop_role(smraw, bid, pin, pout, l, Wout);
    } else {
        gemm_role(smraw, bid - NCTAS_LOOP);
    }
}

// ---------------- softmax kernel (tiny) ----------------
__global__ __launch_bounds__(BATCH) void softmax_kernel(float* __restrict__ out) {
    const int b = threadIdx.x;
    float v[OUTD];
    #pragma unroll
    for (int o = 0; o < OUTD; o++) v[o] = g_logits[b * OUTD + o];
    float mx = v[0];
    #pragma unroll
    for (int o = 1; o < OUTD; o++) mx = fmaxf(mx, v[o]);
    float e[OUTD], sum = 0.0f;
    #pragma unroll
    for (int o = 0; o < OUTD; o++) { e[o] = expf(v[o] - mx); sum += e[o]; }
    float inv = 1.0f / sum;
    #pragma unroll
    for (int o = 0; o < OUTD; o++) out[b * OUTD + o] = e[o] * inv;
}

// ---------------- launch ----------------
extern "C" void kernel_launch(void* const* d_in, const int* in_sizes, int n_in,
                              void* d_out, int out_size) {
    const float* spk  = (const float*)d_in[0];
    const float* Win  = (const float*)d_in[1];
    const float* Wout = (const float*)d_in[2];
    const float* pin  = (const float*)d_in[3];
    const float* pout = (const float*)d_in[4];
    const float* l    = (const float*)d_in[5];
    float* out = (float*)d_out;

    static bool init = false;
    if (!init) {
        cudaFuncSetAttribute(fused_kernel, cudaFuncAttributeMaxDynamicSharedMemorySize, FUSED_SMEM);
        init = true;
    }

    prep_kernel<<<PREP_BLKS, 256>>>(spk, Win);
    fused_kernel<<<NCTAS_ALL, 256, FUSED_SMEM>>>(pin, pout, l, Wout);
    softmax_kernel<<<1, BATCH>>>(out);
}

// round 14
// speedup vs baseline: 1.3102x; 1.3102x over previous
#include <cuda_runtime.h>
#include <cuda_bf16.h>
#include <cuda_fp16.h>
#include <cooperative_groups.h>
#include <math.h>
#include <stdint.h>

namespace cg = cooperative_groups;

#define T_STEPS 100
#define BATCH   256
#define IN_DIM  784
#define HID     1024
#define OUTD    10
#define P_DIM   64
#define ALPHA   0.05f   // DT / TAUM

#define M_TOT   (T_STEPS * BATCH)   // 25600
#define K_PAD   832                 // 13 * 64 fp16 (128B rows)
#define N_CHUNK 13
#define TILES_PER_T 16

#define NCTAS_LOOP 64
#define NCTAS_GEMM 1600
#define NCTAS_ALL  (NCTAS_LOOP + NCTAS_GEMM)

#define PREP_WIN_BLKS 416           // HID*104/256
#define PREP_SPK_BLKS 10400         // M_TOT*104/256
#define PREP_BLKS     (PREP_WIN_BLKS + PREP_SPK_BLKS)

// ---------------- scratch (static device globals) ----------------
__device__ __half g_Iin[(size_t)T_STEPS * BATCH * HID];   // fp16 input currents
__device__ float  g_logits[BATCH * OUTD];
__device__ __half g_spkh[(size_t)M_TOT * K_PAD];
__device__ __half g_WinH[(size_t)HID * K_PAD];
__device__ unsigned int g_tdone[T_STEPS];

// ---------------- helpers ----------------
__device__ __forceinline__ uint32_t smem_u32(const void* p) {
    uint32_t a;
    asm("{ .reg .u64 t; cvta.to.shared.u64 t, %1; cvt.u32.u64 %0, t; }" : "=r"(a) : "l"(p));
    return a;
}
#define SWZ128(o) ((o) ^ (((o) >> 3) & 0x70))
#define CP_COMMIT() asm volatile("cp.async.commit_group;" ::: "memory")
#define CP_WAIT(n)  asm volatile("cp.async.wait_group %0;" :: "n"(n) : "memory")

__device__ __forceinline__ void ldm_x4(uint32_t* r, uint32_t addr) {
    asm volatile("ldmatrix.sync.aligned.m8n8.x4.shared.b16 {%0,%1,%2,%3}, [%4];"
                 : "=r"(r[0]), "=r"(r[1]), "=r"(r[2]), "=r"(r[3]) : "r"(addr));
}
__device__ __forceinline__ void mma_bf16(float* c, const uint32_t* a, uint32_t b0, uint32_t b1) {
    asm volatile("mma.sync.aligned.m16n8k16.row.col.f32.bf16.bf16.f32 "
                 "{%0,%1,%2,%3}, {%4,%5,%6,%7}, {%8,%9}, {%0,%1,%2,%3};"
                 : "+f"(c[0]), "+f"(c[1]), "+f"(c[2]), "+f"(c[3])
                 : "r"(a[0]), "r"(a[1]), "r"(a[2]), "r"(a[3]), "r"(b0), "r"(b1));
}
__device__ __forceinline__ void mma_f16(float* c, const uint32_t* a, uint32_t b0, uint32_t b1) {
    asm volatile("mma.sync.aligned.m16n8k16.row.col.f32.f16.f16.f32 "
                 "{%0,%1,%2,%3}, {%4,%5,%6,%7}, {%8,%9}, {%0,%1,%2,%3};"
                 : "+f"(c[0]), "+f"(c[1]), "+f"(c[2]), "+f"(c[3])
                 : "r"(a[0]), "r"(a[1]), "r"(a[2]), "r"(a[3]), "r"(b0), "r"(b1));
}

// ---------------- merged prep kernel (verified 18us, DRAM-bound) ----------------
__global__ void prep_kernel(const float* __restrict__ spk, const float* __restrict__ Win) {
    const int blk = blockIdx.x;
    const int tid = threadIdx.x;
    if (blk == 0 && tid < T_STEPS) g_tdone[tid] = 0u;
    if (blk < 10 && blk * 256 + tid < BATCH * OUTD) g_logits[blk * 256 + tid] = 0.0f;

    if (blk < PREP_WIN_BLKS) {
        int i   = blk * 256 + tid;                 // < HID*104
        int row = i / (K_PAD / 8);
        int c0  = (i % (K_PAD / 8)) * 8;
        __half v[8];
        if (c0 < IN_DIM) {
            const float4* src = (const float4*)&Win[(size_t)row * IN_DIM + c0];
            float4 f0 = src[0], f1 = src[1];
            v[0] = __float2half_rn(f0.x); v[1] = __float2half_rn(f0.y);
            v[2] = __float2half_rn(f0.z); v[3] = __float2half_rn(f0.w);
            v[4] = __float2half_rn(f1.x); v[5] = __float2half_rn(f1.y);
            v[6] = __float2half_rn(f1.z); v[7] = __float2half_rn(f1.w);
        } else {
            #pragma unroll
            for (int j = 0; j < 8; j++) v[j] = __float2half_rn(0.0f);
        }
        *(uint4*)&g_WinH[(size_t)row * K_PAD + c0] = *(uint4*)v;
    } else {
        int i   = (blk - PREP_WIN_BLKS) * 256 + tid;   // < M_TOT*104
        int row = i / (K_PAD / 8);
        int c0  = (i % (K_PAD / 8)) * 8;
        __half v[8];
        if (c0 < IN_DIM) {
            const float4* src = (const float4*)&spk[(size_t)row * IN_DIM + c0];
            float4 f0 = src[0], f1 = src[1];
            v[0] = __float2half_rn(f0.x); v[1] = __float2half_rn(f0.y);
            v[2] = __float2half_rn(f0.z); v[3] = __float2half_rn(f0.w);
            v[4] = __float2half_rn(f1.x); v[5] = __float2half_rn(f1.y);
            v[6] = __float2half_rn(f1.z); v[7] = __float2half_rn(f1.w);
        } else {
            #pragma unroll
            for (int j = 0; j < 8; j++) v[j] = __float2half_rn(0.0f);
        }
        *(uint4*)&g_spkh[(size_t)row * K_PAD + c0] = *(uint4*)v;
    }
}

// ---------------- gemm role (fp16, fp16 Iin epilogue) ----------------
#define TILE_BYTES  16384
#define STAGE_BYTES (2 * TILE_BYTES)
#define GEMM_SMEM   (2 * STAGE_BYTES)   // 65536

__device__ __forceinline__ void copy_tile(uint32_t sdst, const __half* __restrict__ g,
                                          int row0, int k0, int tid) {
    #pragma unroll
    for (int j = 0; j < 4; j++) {
        int i   = tid + j * 256;
        int row = i >> 3;
        int cb  = i & 7;
        const void* gp = g + (size_t)(row0 + row) * K_PAD + k0 + cb * 8;
        uint32_t so = sdst + SWZ128(row * 128 + cb * 16);
        asm volatile("cp.async.cg.shared.global [%0], [%1], 16;" :: "r"(so), "l"(gp));
    }
}

__device__ void gemm_role(char* smraw, int gid) {
    const uint32_t sb  = smem_u32(smraw);
    const int tid  = threadIdx.x;
    const int wid  = tid >> 5;
    const int lane = tid & 31;
    const int m0 = (gid >> 3) * 128;
    const int n0 = (gid & 7) * 128;
    const int wm = (wid & 3) * 32;
    const int wn = (wid >> 2) * 64;

    const uint32_t stA[2] = {sb,                  sb + STAGE_BYTES};
    const uint32_t stB[2] = {stA[0] + TILE_BYTES, stA[1] + TILE_BYTES};

    float acc[2][8][4];
    #pragma unroll
    for (int mi = 0; mi < 2; mi++)
        #pragma unroll
        for (int nj = 0; nj < 8; nj++)
            #pragma unroll
            for (int q = 0; q < 4; q++) acc[mi][nj][q] = 0.0f;

    copy_tile(stA[0], g_spkh, m0, 0, tid);
    copy_tile(stB[0], g_WinH, n0, 0, tid);
    CP_COMMIT();
    copy_tile(stA[1], g_spkh, m0, 64, tid);
    copy_tile(stB[1], g_WinH, n0, 64, tid);
    CP_COMMIT();

    const int arow = wm + (lane & 15);
    const int acolL = (lane >> 4) << 4;
    const int brow = (lane & 7) + ((lane >> 4) << 3);
    const int bcolL = ((lane >> 3) & 1) << 4;

    for (int k = 0; k < N_CHUNK; k++) {
        const int s = k & 1;
        if (k < N_CHUNK - 1) CP_WAIT(1); else CP_WAIT(0);
        __syncthreads();

        #pragma unroll
        for (int ks = 0; ks < 4; ks++) {
            const int kb = ks * 32;
            uint32_t af[2][4];
            ldm_x4(af[0], stA[s] + SWZ128((arow)      * 128 + kb + acolL));
            ldm_x4(af[1], stA[s] + SWZ128((arow + 16) * 128 + kb + acolL));

            #pragma unroll
            for (int nb = 0; nb < 4; nb++) {
                const uint32_t boff = SWZ128((wn + nb * 16 + brow) * 128 + kb + bcolL);
                uint32_t bh[4];
                ldm_x4(bh, stB[s] + boff);
                #pragma unroll
                for (int mi = 0; mi < 2; mi++) {
                    mma_f16(acc[mi][nb * 2 + 0], af[mi], bh[0], bh[1]);
                    mma_f16(acc[mi][nb * 2 + 1], af[mi], bh[2], bh[3]);
                }
            }
        }
        __syncthreads();

        if (k + 2 < N_CHUNK) {
            const int k0 = (k + 2) * 64;
            copy_tile(stA[s], g_spkh, m0, k0, tid);
            copy_tile(stB[s], g_WinH, n0, k0, tid);
            CP_COMMIT();
        }
    }

    const int r0 = lane >> 2;
    const int c0 = (lane & 3) * 2;
    #pragma unroll
    for (int mi = 0; mi < 2; mi++) {
        #pragma unroll
        for (int nj = 0; nj < 8; nj++) {
            const int row = m0 + wm + mi * 16 + r0;
            const int col = n0 + wn + nj * 8 + c0;
            __half2 v01 = __floats2half2_rn(acc[mi][nj][0], acc[mi][nj][1]);
            __half2 v23 = __floats2half2_rn(acc[mi][nj][2], acc[mi][nj][3]);
            *(__half2*)&g_Iin[(size_t)row * HID + col]       = v01;
            *(__half2*)&g_Iin[(size_t)(row + 8) * HID + col] = v23;
        }
    }

    __syncthreads();
    if (tid == 0) {
        __threadfence();
        atomicAdd(&g_tdone[gid >> 4], 1u);
    }
}

// ---------------- loop role: cluster.sync exchange (R12-verified) + fused readout ----------------
#define CLUSTER_N   4
#define ROWS_PER_CL 16
#define H_PER_CTA   256

#define L_OFF_POUT  0        // 32KB
#define L_OFF_WPL   32768    // 32KB
#define L_OFF_TH    65536    // 8KB
#define L_OFF_U     73728    // 2KB
#define L_OFF_UPART 75776    // 8KB (reused as wred at end)
#define L_OFF_MBOX  83968    // 16KB
#define LOOP_SMEM   100352

#define FUSED_SMEM  (LOOP_SMEM > GEMM_SMEM ? LOOP_SMEM : GEMM_SMEM)

__device__ void loop_role(char* smraw, int bid,
                          const float* __restrict__ pin, const float* __restrict__ pout,
                          const float* __restrict__ l, const float* __restrict__ Wout) {
    const uint32_t sb = smem_u32(smraw);

    cg::cluster_group cl = cg::this_cluster();
    const int rank = cl.block_rank();
    const int cidx = bid / CLUSTER_N;
    const int b0   = cidx * ROWS_PER_CL;
    const int H0   = rank * H_PER_CTA;
    const int tid  = threadIdx.x;
    const int wid  = tid >> 5;
    const int lane = tid & 31;

    for (int i = tid; i < H_PER_CTA * P_DIM; i += 256) {
        int hl = i >> 6;
        int p  = i & 63;
        float pv = pout[(size_t)(H0 + hl) * P_DIM + p];
        *(__nv_bfloat16*)(smraw + L_OFF_POUT + (hl >> 6) * 8192
                          + SWZ128(p * 128 + (hl & 63) * 2)) = __float2bfloat16(pv);
        float wv = pin[(size_t)(H0 + hl) * P_DIM + p] * l[p];
        *(__nv_bfloat16*)(smraw + L_OFF_WPL + SWZ128(hl * 128 + p * 2)) = __float2bfloat16(wv);
    }
    for (int i = tid; i < (8192 + 2048) / 4; i += 256)
        ((uint32_t*)(smraw + L_OFF_TH))[i] = 0;

    const int kg   = wid >> 2;
    const int wn16 = (wid & 3) * 16;
    const int aRow = lane & 15;
    const int aCol = (lane >> 4) << 4;
    const int bRow = (lane & 7) + ((lane >> 4) << 3);
    const int bCol = ((lane >> 3) & 1) << 4;
    const int r    = lane >> 2;
    const int c2   = (lane & 3) * 2;

    const int r_e  = tid >> 4;
    const int pe   = (tid & 15) * 4;
    char* mboxLocal = smraw + L_OFF_MBOX;
    char* peerMb[CLUSTER_N];
    #pragma unroll
    for (int rk = 0; rk < CLUSTER_N; rk++)
        peerMb[rk] = (char*)cl.map_shared_rank((void*)mboxLocal, rk);

    float2 memv[8], rmv[8];
    #pragma unroll
    for (int j = 0; j < 8; j++) { memv[j] = make_float2(0.f, 0.f); rmv[j] = make_float2(-2.f, -2.f); }

    cl.sync();

    for (int t = 0; t < T_STEPS; t++) {
        if (tid == 0) {
            volatile unsigned int* f = &g_tdone[t];
            while (*f < TILES_PER_T) {}
            __threadfence();
        }
        __syncthreads();
        const int buf = t & 1;

        float2 iin[8];
        {
            const size_t base = ((size_t)t * BATCH + b0 + r) * HID + H0 + wid * 32 + c2;
            #pragma unroll
            for (int nb = 0; nb < 2; nb++)
                #pragma unroll
                for (int sub = 0; sub < 2; sub++) {
                    uint32_t w0 = __ldcs((const uint32_t*)&g_Iin[base + nb * 16 + sub * 8]);
                    uint32_t w1 = __ldcs((const uint32_t*)&g_Iin[base + 8 * HID + nb * 16 + sub * 8]);
                    iin[nb * 2 + sub]     = __half22float2(*(__half2*)&w0);
                    iin[4 + nb * 2 + sub] = __half22float2(*(__half2*)&w1);
                }
        }

        // ---- phase A: partial U[16r x 16p] over h-half kg ----
        float accA[2][4] = {{0.f,0.f,0.f,0.f},{0.f,0.f,0.f,0.f}};
        #pragma unroll
        for (int cc = 0; cc < 2; cc++) {
            const int ch = kg * 2 + cc;
            const uint32_t thB = sb + L_OFF_TH + ch * 2048;
            const uint32_t poB = sb + L_OFF_POUT + ch * 8192;
            #pragma unroll
            for (int ks = 0; ks < 4; ks++) {
                const int kb = ks * 32;
                uint32_t af[4], bf[4];
                ldm_x4(af, thB + SWZ128(aRow * 128 + kb + aCol));
                ldm_x4(bf, poB + SWZ128((wn16 + bRow) * 128 + kb + bCol));
                mma_bf16(accA[0], af, bf[0], bf[1]);
                mma_bf16(accA[1], af, bf[2], bf[3]);
            }
        }
        {
            float* up = (float*)(smraw + L_OFF_UPART);
            const int rowA = (kg * 16 + r) * 64 + wn16;
            const int rowB = (kg * 16 + r + 8) * 64 + wn16;
            *(float2*)&up[rowA + 0 + c2] = make_float2(accA[0][0], accA[0][1]);
            *(float2*)&up[rowA + 8 + c2] = make_float2(accA[1][0], accA[1][1]);
            *(float2*)&up[rowB + 0 + c2] = make_float2(accA[0][2], accA[0][3]);
            *(float2*)&up[rowB + 8 + c2] = make_float2(accA[1][2], accA[1][3]);
        }
        __syncthreads();

        // pair-sum kg halves, pack bf16, scatter to all ranks
        {
            const float* up = (const float*)(smraw + L_OFF_UPART);
            float v0 = up[r_e * 64 + pe + 0] + up[(16 + r_e) * 64 + pe + 0];
            float v1 = up[r_e * 64 + pe + 1] + up[(16 + r_e) * 64 + pe + 1];
            float v2 = up[r_e * 64 + pe + 2] + up[(16 + r_e) * 64 + pe + 2];
            float v3 = up[r_e * 64 + pe + 3] + up[(16 + r_e) * 64 + pe + 3];
            uint2 pk;
            __nv_bfloat162 b01 = __floats2bfloat162_rn(v0, v1);
            __nv_bfloat162 b23 = __floats2bfloat162_rn(v2, v3);
            pk.x = *(uint32_t*)&b01;
            pk.y = *(uint32_t*)&b23;
            const int moff = ((buf * CLUSTER_N + rank) * 16 + r_e) * 128 + pe * 2;
            #pragma unroll
            for (int rk = 0; rk < CLUSTER_N; rk++)
                *(uint2*)(peerMb[rk] + moff) = pk;
        }
        cl.sync();

        // reduce 4 ranks -> U bf16 tile
        {
            float s0 = 0.f, s1 = 0.f, s2 = 0.f, s3 = 0.f;
            #pragma unroll
            for (int rk = 0; rk < CLUSTER_N; rk++) {
                uint2 q = *(uint2*)(mboxLocal + ((buf * CLUSTER_N + rk) * 16 + r_e) * 128 + pe * 2);
                float2 f01 = __bfloat1622float2(*(__nv_bfloat162*)&q.x);
                float2 f23 = __bfloat1622float2(*(__nv_bfloat162*)&q.y);
                s0 += f01.x; s1 += f01.y; s2 += f23.x; s3 += f23.y;
            }
            uint2 pk;
            __nv_bfloat162 b01 = __floats2bfloat162_rn(s0, s1);
            __nv_bfloat162 b23 = __floats2bfloat162_rn(s2, s3);
            pk.x = *(uint32_t*)&b01;
            pk.y = *(uint32_t*)&b23;
            *(uint2*)(smraw + L_OFF_U + SWZ128(r_e * 128 + pe * 2)) = pk;
        }
        __syncthreads();

        // ---- phase B ----
        float accB[2][2][4];
        #pragma unroll
        for (int nb = 0; nb < 2; nb++)
            #pragma unroll
            for (int sub = 0; sub < 2; sub++)
                #pragma unroll
                for (int q = 0; q < 4; q++) accB[nb][sub][q] = 0.f;

        const uint32_t uB = sb + L_OFF_U;
        const uint32_t wB = sb + L_OFF_WPL;
        #pragma unroll
        for (int ks = 0; ks < 4; ks++) {
            const int kb = ks * 32;
            uint32_t af[4];
            ldm_x4(af, uB + SWZ128(aRow * 128 + kb + aCol));
            #pragma unroll
            for (int nb = 0; nb < 2; nb++) {
                uint32_t bf[4];
                ldm_x4(bf, wB + SWZ128((wid * 32 + nb * 16 + bRow) * 128 + kb + bCol));
                mma_bf16(accB[nb][0], af, bf[0], bf[1]);
                mma_bf16(accB[nb][1], af, bf[2], bf[3]);
            }
        }

        #pragma unroll
        for (int nb = 0; nb < 2; nb++) {
            #pragma unroll
            for (int sub = 0; sub < 2; sub++) {
                const int j  = nb * 2 + sub;
                const int hc = wid * 32 + nb * 16 + sub * 8 + c2;
                const uint32_t thBase = (uint32_t)(L_OFF_TH + (hc >> 6) * 2048);
                {
                    float m0 = (iin[j].x + accB[nb][sub][0] - memv[j].x) * ALPHA;
                    float m1 = (iin[j].y + accB[nb][sub][1] - memv[j].y) * ALPHA;
                    memv[j].x = m0;  memv[j].y = m1;
                    float tv0 = tanhf(m0), tv1 = tanhf(m1);
                    rmv[j].x = fmaxf(rmv[j].x, tv0);
                    rmv[j].y = fmaxf(rmv[j].y, tv1);
                    *(__nv_bfloat162*)(smraw + thBase + SWZ128(r * 128 + (hc & 63) * 2)) =
                        __floats2bfloat162_rn(tv0, tv1);
                }
                {
                    float m0 = (iin[4 + j].x + accB[nb][sub][2] - memv[4 + j].x) * ALPHA;
                    float m1 = (iin[4 + j].y + accB[nb][sub][3] - memv[4 + j].y) * ALPHA;
                    memv[4 + j].x = m0;  memv[4 + j].y = m1;
                    float tv0 = tanhf(m0), tv1 = tanhf(m1);
                    rmv[4 + j].x = fmaxf(rmv[4 + j].x, tv0);
                    rmv[4 + j].y = fmaxf(rmv[4 + j].y, tv1);
                    *(__nv_bfloat162*)(smraw + thBase + SWZ128((r + 8) * 128 + (hc & 63) * 2)) =
                        __floats2bfloat162_rn(tv0, tv1);
                }
            }
        }
    }

    // ---- fused readout partials: logits[b][o] += sum_h rm[b][h] * Wout[o][h] ----
    float pr0[OUTD], pr1[OUTD];
    #pragma unroll
    for (int o = 0; o < OUTD; o++) { pr0[o] = 0.f; pr1[o] = 0.f; }
    #pragma unroll
    for (int nb = 0; nb < 2; nb++)
        #pragma unroll
        for (int sub = 0; sub < 2; sub++) {
            const int j  = nb * 2 + sub;
            const int hc = wid * 32 + nb * 16 + sub * 8 + c2;
            #pragma unroll
            for (int o = 0; o < OUTD; o++) {
                float2 wv = *(const float2*)&Wout[(size_t)o * HID + H0 + hc];
                pr0[o] = fmaf(rmv[j].x,     wv.x, fmaf(rmv[j].y,     wv.y, pr0[o]));
                pr1[o] = fmaf(rmv[4 + j].x, wv.x, fmaf(rmv[4 + j].y, wv.y, pr1[o]));
            }
        }
    #pragma unroll
    for (int o = 0; o < OUTD; o++) {
        pr0[o] += __shfl_xor_sync(0xffffffffu, pr0[o], 1);
        pr0[o] += __shfl_xor_sync(0xffffffffu, pr0[o], 2);
        pr1[o] += __shfl_xor_sync(0xffffffffu, pr1[o], 1);
        pr1[o] += __shfl_xor_sync(0xffffffffu, pr1[o], 2);
    }
    __syncthreads();   // UPART reads done; reuse as wred[8][16][12]
    float* wred = (float*)(smraw + L_OFF_UPART);
    if ((lane & 3) == 0) {
        #pragma unroll
        for (int o = 0; o < OUTD; o++) {
            wred[(wid * 16 + r)     * 12 + o] = pr0[o];
            wred[(wid * 16 + r + 8) * 12 + o] = pr1[o];
        }
    }
    __syncthreads();
    if (tid < ROWS_PER_CL * OUTD) {
        int row = tid / OUTD;
        int o   = tid % OUTD;
        float s = 0.f;
        #pragma unroll
        for (int w = 0; w < 8; w++) s += wred[(w * 16 + row) * 12 + o];
        atomicAdd(&g_logits[(b0 + row) * OUTD + o], s);
    }
    cl.sync();   // no CTA exits while peer DSMEM traffic could be in flight
}

// ---------------- fused heterogeneous kernel ----------------
__global__ void __cluster_dims__(CLUSTER_N, 1, 1) __launch_bounds__(256, 2)
fused_kernel(const float* __restrict__ pin, const float* __restrict__ pout,
             const float* __restrict__ l, const float* __restrict__ Wout) {
    extern __shared__ char smraw[];
    const int bid = blockIdx.x;
    if (bid < NCTAS_LOOP) {
        loop_role(smraw, bid, pin, pout, l, Wout);
    } else {
        gemm_role(smraw, bid - NCTAS_LOOP);
    }
}

// ---------------- softmax kernel (tiny) ----------------
__global__ __launch_bounds__(BATCH) void softmax_kernel(float* __restrict__ out) {
    const int b = threadIdx.x;
    float v[OUTD];
    #pragma unroll
    for (int o = 0; o < OUTD; o++) v[o] = g_logits[b * OUTD + o];
    float mx = v[0];
    #pragma unroll
    for (int o = 1; o < OUTD; o++) mx = fmaxf(mx, v[o]);
    float e[OUTD], sum = 0.0f;
    #pragma unroll
    for (int o = 0; o < OUTD; o++) { e[o] = expf(v[o] - mx); sum += e[o]; }
    float inv = 1.0f / sum;
    #pragma unroll
    for (int o = 0; o < OUTD; o++) out[b * OUTD + o] = e[o] * inv;
}

// ---------------- launch ----------------
extern "C" void kernel_launch(void* const* d_in, const int* in_sizes, int n_in,
                              void* d_out, int out_size) {
    const float* spk  = (const float*)d_in[0];
    const float* Win  = (const float*)d_in[1];
    const float* Wout = (const float*)d_in[2];
    const float* pin  = (const float*)d_in[3];
    const float* pout = (const float*)d_in[4];
    const float* l    = (const float*)d_in[5];
    float* out = (float*)d_out;

    static bool init = false;
    if (!init) {
        cudaFuncSetAttribute(fused_kernel, cudaFuncAttributeMaxDynamicSharedMemorySize, FUSED_SMEM);
        init = true;
    }

    prep_kernel<<<PREP_BLKS, 256>>>(spk, Win);
    fused_kernel<<<NCTAS_ALL, 256, FUSED_SMEM>>>(pin, pout, l, Wout);
    softmax_kernel<<<1, BATCH>>>(out);
}

// round 15
// speedup vs baseline: 1.3120x; 1.0014x over previous
#include <cuda_runtime.h>
#include <cuda_bf16.h>
#include <cuda_fp16.h>
#include <cooperative_groups.h>
#include <math.h>
#include <stdint.h>

namespace cg = cooperative_groups;

#define T_STEPS 100
#define BATCH   256
#define IN_DIM  784
#define HID     1024
#define OUTD    10
#define P_DIM   64
#define ALPHA   0.05f   // DT / TAUM

#define M_TOT   (T_STEPS * BATCH)   // 25600
#define K_PAD   832                 // 13 * 64 fp16 (128B rows)
#define N_CHUNK 13
#define TILES_PER_T 16

#define NCTAS_LOOP 64
#define NCTAS_GEMM 1600
#define NCTAS_ALL  (NCTAS_LOOP + NCTAS_GEMM)

#define PREP_WIN_BLKS 416           // HID*104/256
#define PREP_SPK_BLKS 10400         // M_TOT*104/256
#define PREP_BLKS     (PREP_WIN_BLKS + PREP_SPK_BLKS)

// ---------------- scratch (static device globals) ----------------
__device__ __half g_Iin[(size_t)T_STEPS * BATCH * HID];   // fp16 input currents
__device__ float  g_logits[BATCH * OUTD];
__device__ __half g_spkh[(size_t)M_TOT * K_PAD];
__device__ __half g_WinH[(size_t)HID * K_PAD];
__device__ unsigned int g_tdone[T_STEPS];

// ---------------- helpers ----------------
__device__ __forceinline__ uint32_t smem_u32(const void* p) {
    uint32_t a;
    asm("{ .reg .u64 t; cvta.to.shared.u64 t, %1; cvt.u32.u64 %0, t; }" : "=r"(a) : "l"(p));
    return a;
}
#define SWZ128(o) ((o) ^ (((o) >> 3) & 0x70))
#define CP_COMMIT() asm volatile("cp.async.commit_group;" ::: "memory")
#define CP_WAIT(n)  asm volatile("cp.async.wait_group %0;" :: "n"(n) : "memory")

__device__ __forceinline__ void ldm_x4(uint32_t* r, uint32_t addr) {
    asm volatile("ldmatrix.sync.aligned.m8n8.x4.shared.b16 {%0,%1,%2,%3}, [%4];"
                 : "=r"(r[0]), "=r"(r[1]), "=r"(r[2]), "=r"(r[3]) : "r"(addr));
}
__device__ __forceinline__ void mma_bf16(float* c, const uint32_t* a, uint32_t b0, uint32_t b1) {
    asm volatile("mma.sync.aligned.m16n8k16.row.col.f32.bf16.bf16.f32 "
                 "{%0,%1,%2,%3}, {%4,%5,%6,%7}, {%8,%9}, {%0,%1,%2,%3};"
                 : "+f"(c[0]), "+f"(c[1]), "+f"(c[2]), "+f"(c[3])
                 : "r"(a[0]), "r"(a[1]), "r"(a[2]), "r"(a[3]), "r"(b0), "r"(b1));
}
__device__ __forceinline__ void mma_f16(float* c, const uint32_t* a, uint32_t b0, uint32_t b1) {
    asm volatile("mma.sync.aligned.m16n8k16.row.col.f32.f16.f16.f32 "
                 "{%0,%1,%2,%3}, {%4,%5,%6,%7}, {%8,%9}, {%0,%1,%2,%3};"
                 : "+f"(c[0]), "+f"(c[1]), "+f"(c[2]), "+f"(c[3])
                 : "r"(a[0]), "r"(a[1]), "r"(a[2]), "r"(a[3]), "r"(b0), "r"(b1));
}

// ---------------- merged prep kernel (verified 18us, DRAM-bound) ----------------
__global__ void prep_kernel(const float* __restrict__ spk, const float* __restrict__ Win) {
    const int blk = blockIdx.x;
    const int tid = threadIdx.x;
    if (blk == 0 && tid < T_STEPS) g_tdone[tid] = 0u;
    if (blk < 10 && blk * 256 + tid < BATCH * OUTD) g_logits[blk * 256 + tid] = 0.0f;

    if (blk < PREP_WIN_BLKS) {
        int i   = blk * 256 + tid;                 // < HID*104
        int row = i / (K_PAD / 8);
        int c0  = (i % (K_PAD / 8)) * 8;
        __half v[8];
        if (c0 < IN_DIM) {
            const float4* src = (const float4*)&Win[(size_t)row * IN_DIM + c0];
            float4 f0 = src[0], f1 = src[1];
            v[0] = __float2half_rn(f0.x); v[1] = __float2half_rn(f0.y);
            v[2] = __float2half_rn(f0.z); v[3] = __float2half_rn(f0.w);
            v[4] = __float2half_rn(f1.x); v[5] = __float2half_rn(f1.y);
            v[6] = __float2half_rn(f1.z); v[7] = __float2half_rn(f1.w);
        } else {
            #pragma unroll
            for (int j = 0; j < 8; j++) v[j] = __float2half_rn(0.0f);
        }
        *(uint4*)&g_WinH[(size_t)row * K_PAD + c0] = *(uint4*)v;
    } else {
        int i   = (blk - PREP_WIN_BLKS) * 256 + tid;   // < M_TOT*104
        int row = i / (K_PAD / 8);
        int c0  = (i % (K_PAD / 8)) * 8;
        __half v[8];
        if (c0 < IN_DIM) {
            const float4* src = (const float4*)&spk[(size_t)row * IN_DIM + c0];
            float4 f0 = src[0], f1 = src[1];
            v[0] = __float2half_rn(f0.x); v[1] = __float2half_rn(f0.y);
            v[2] = __float2half_rn(f0.z); v[3] = __float2half_rn(f0.w);
            v[4] = __float2half_rn(f1.x); v[5] = __float2half_rn(f1.y);
            v[6] = __float2half_rn(f1.z); v[7] = __float2half_rn(f1.w);
        } else {
            #pragma unroll
            for (int j = 0; j < 8; j++) v[j] = __float2half_rn(0.0f);
        }
        *(uint4*)&g_spkh[(size_t)row * K_PAD + c0] = *(uint4*)v;
    }
}

// ---------------- gemm role (fp16, fp16 Iin epilogue) — unchanged ----------------
#define TILE_BYTES  16384
#define STAGE_BYTES (2 * TILE_BYTES)
#define GEMM_SMEM   (2 * STAGE_BYTES)   // 65536

__device__ __forceinline__ void copy_tile(uint32_t sdst, const __half* __restrict__ g,
                                          int row0, int k0, int tid) {
    #pragma unroll
    for (int j = 0; j < 4; j++) {
        int i   = tid + j * 256;
        int row = i >> 3;
        int cb  = i & 7;
        const void* gp = g + (size_t)(row0 + row) * K_PAD + k0 + cb * 8;
        uint32_t so = sdst + SWZ128(row * 128 + cb * 16);
        asm volatile("cp.async.cg.shared.global [%0], [%1], 16;" :: "r"(so), "l"(gp));
    }
}

__device__ void gemm_role(char* smraw, int gid) {
    const uint32_t sb  = smem_u32(smraw);
    const int tid  = threadIdx.x;
    const int wid  = tid >> 5;
    const int lane = tid & 31;
    const int m0 = (gid >> 3) * 128;
    const int n0 = (gid & 7) * 128;
    const int wm = (wid & 3) * 32;
    const int wn = (wid >> 2) * 64;

    const uint32_t stA[2] = {sb,                  sb + STAGE_BYTES};
    const uint32_t stB[2] = {stA[0] + TILE_BYTES, stA[1] + TILE_BYTES};

    float acc[2][8][4];
    #pragma unroll
    for (int mi = 0; mi < 2; mi++)
        #pragma unroll
        for (int nj = 0; nj < 8; nj++)
            #pragma unroll
            for (int q = 0; q < 4; q++) acc[mi][nj][q] = 0.0f;

    copy_tile(stA[0], g_spkh, m0, 0, tid);
    copy_tile(stB[0], g_WinH, n0, 0, tid);
    CP_COMMIT();
    copy_tile(stA[1], g_spkh, m0, 64, tid);
    copy_tile(stB[1], g_WinH, n0, 64, tid);
    CP_COMMIT();

    const int arow = wm + (lane & 15);
    const int acolL = (lane >> 4) << 4;
    const int brow = (lane & 7) + ((lane >> 4) << 3);
    const int bcolL = ((lane >> 3) & 1) << 4;

    for (int k = 0; k < N_CHUNK; k++) {
        const int s = k & 1;
        if (k < N_CHUNK - 1) CP_WAIT(1); else CP_WAIT(0);
        __syncthreads();

        #pragma unroll
        for (int ks = 0; ks < 4; ks++) {
            const int kb = ks * 32;
            uint32_t af[2][4];
            ldm_x4(af[0], stA[s] + SWZ128((arow)      * 128 + kb + acolL));
            ldm_x4(af[1], stA[s] + SWZ128((arow + 16) * 128 + kb + acolL));

            #pragma unroll
            for (int nb = 0; nb < 4; nb++) {
                const uint32_t boff = SWZ128((wn + nb * 16 + brow) * 128 + kb + bcolL);
                uint32_t bh[4];
                ldm_x4(bh, stB[s] + boff);
                #pragma unroll
                for (int mi = 0; mi < 2; mi++) {
                    mma_f16(acc[mi][nb * 2 + 0], af[mi], bh[0], bh[1]);
                    mma_f16(acc[mi][nb * 2 + 1], af[mi], bh[2], bh[3]);
                }
            }
        }
        __syncthreads();

        if (k + 2 < N_CHUNK) {
            const int k0 = (k + 2) * 64;
            copy_tile(stA[s], g_spkh, m0, k0, tid);
            copy_tile(stB[s], g_WinH, n0, k0, tid);
            CP_COMMIT();
        }
    }

    const int r0 = lane >> 2;
    const int c0 = (lane & 3) * 2;
    #pragma unroll
    for (int mi = 0; mi < 2; mi++) {
        #pragma unroll
        for (int nj = 0; nj < 8; nj++) {
            const int row = m0 + wm + mi * 16 + r0;
            const int col = n0 + wn + nj * 8 + c0;
            __half2 v01 = __floats2half2_rn(acc[mi][nj][0], acc[mi][nj][1]);
            __half2 v23 = __floats2half2_rn(acc[mi][nj][2], acc[mi][nj][3]);
            *(__half2*)&g_Iin[(size_t)row * HID + col]       = v01;
            *(__half2*)&g_Iin[(size_t)(row + 8) * HID + col] = v23;
        }
    }

    __syncthreads();
    if (tid == 0) {
        __threadfence();
        atomicAdd(&g_tdone[gid >> 4], 1u);
    }
}

// ---------------- loop role: pipelined Iin prefetch ----------------
#define CLUSTER_N   4
#define ROWS_PER_CL 16
#define H_PER_CTA   256

#define L_OFF_POUT  0        // 32KB
#define L_OFF_WPL   32768    // 32KB
#define L_OFF_TH    65536    // 8KB
#define L_OFF_U     73728    // 2KB
#define L_OFF_UPART 75776    // 8KB (reused as wred at end)
#define L_OFF_MBOX  83968    // 16KB
#define LOOP_SMEM   100352

#define FUSED_SMEM  (LOOP_SMEM > GEMM_SMEM ? LOOP_SMEM : GEMM_SMEM)

__device__ void loop_role(char* smraw, int bid,
                          const float* __restrict__ pin, const float* __restrict__ pout,
                          const float* __restrict__ l, const float* __restrict__ Wout) {
    const uint32_t sb = smem_u32(smraw);

    cg::cluster_group cl = cg::this_cluster();
    const int rank = cl.block_rank();
    const int cidx = bid / CLUSTER_N;
    const int b0   = cidx * ROWS_PER_CL;
    const int H0   = rank * H_PER_CTA;
    const int tid  = threadIdx.x;
    const int wid  = tid >> 5;
    const int lane = tid & 31;

    for (int i = tid; i < H_PER_CTA * P_DIM; i += 256) {
        int hl = i >> 6;
        int p  = i & 63;
        float pv = pout[(size_t)(H0 + hl) * P_DIM + p];
        *(__nv_bfloat16*)(smraw + L_OFF_POUT + (hl >> 6) * 8192
                          + SWZ128(p * 128 + (hl & 63) * 2)) = __float2bfloat16(pv);
        float wv = pin[(size_t)(H0 + hl) * P_DIM + p] * l[p];
        *(__nv_bfloat16*)(smraw + L_OFF_WPL + SWZ128(hl * 128 + p * 2)) = __float2bfloat16(wv);
    }
    for (int i = tid; i < (8192 + 2048) / 4; i += 256)
        ((uint32_t*)(smraw + L_OFF_TH))[i] = 0;

    const int kg   = wid >> 2;
    const int wn16 = (wid & 3) * 16;
    const int aRow = lane & 15;
    const int aCol = (lane >> 4) << 4;
    const int bRow = (lane & 7) + ((lane >> 4) << 3);
    const int bCol = ((lane >> 3) & 1) << 4;
    const int r    = lane >> 2;
    const int c2   = (lane & 3) * 2;

    const int r_e  = tid >> 4;
    const int pe   = (tid & 15) * 4;
    char* mboxLocal = smraw + L_OFF_MBOX;
    char* peerMb[CLUSTER_N];
    #pragma unroll
    for (int rk = 0; rk < CLUSTER_N; rk++)
        peerMb[rk] = (char*)cl.map_shared_rank((void*)mboxLocal, rk);

    float2 memv[8], rmv[8];
    #pragma unroll
    for (int j = 0; j < 8; j++) { memv[j] = make_float2(0.f, 0.f); rmv[j] = make_float2(-2.f, -2.f); }

    // Iin base offset for this thread's 8 outputs (rows r / r+8)
    const size_t iinOff = ((size_t)(b0 + r)) * HID + H0 + wid * 32 + c2;

    // wait for timestep 0's tiles, then cluster barrier covers init + acquire
    if (tid == 0) {
        volatile unsigned int* f = &g_tdone[0];
        while (*f < TILES_PER_T) {}
        __threadfence();
    }
    cl.sync();

    // prefetch Iin[0] as packed half2 payloads (register-neutral vs float2[8])
    uint32_t iinc[8], iinn[8];
    {
        const __half* p0 = &g_Iin[iinOff];
        #pragma unroll
        for (int nb = 0; nb < 2; nb++)
            #pragma unroll
            for (int sub = 0; sub < 2; sub++) {
                iinc[nb * 2 + sub]     = __ldcs((const uint32_t*)(p0 + nb * 16 + sub * 8));
                iinc[4 + nb * 2 + sub] = __ldcs((const uint32_t*)(p0 + 8 * HID + nb * 16 + sub * 8));
            }
    }

    for (int t = 0; t < T_STEPS; t++) {
        __syncthreads();                 // th(t-1) writes visible to phase A
        const int buf = t & 1;

        // ---- phase A: partial U[16r x 16p] over h-half kg ----
        float accA[2][4] = {{0.f,0.f,0.f,0.f},{0.f,0.f,0.f,0.f}};
        #pragma unroll
        for (int cc = 0; cc < 2; cc++) {
            const int ch = kg * 2 + cc;
            const uint32_t thB = sb + L_OFF_TH + ch * 2048;
            const uint32_t poB = sb + L_OFF_POUT + ch * 8192;
            #pragma unroll
            for (int ks = 0; ks < 4; ks++) {
                const int kb = ks * 32;
                uint32_t af[4], bf[4];
                ldm_x4(af, thB + SWZ128(aRow * 128 + kb + aCol));
                ldm_x4(bf, poB + SWZ128((wn16 + bRow) * 128 + kb + bCol));
                mma_bf16(accA[0], af, bf[0], bf[1]);
                mma_bf16(accA[1], af, bf[2], bf[3]);
            }
        }
        {
            float* up = (float*)(smraw + L_OFF_UPART);
            const int rowA = (kg * 16 + r) * 64 + wn16;
            const int rowB = (kg * 16 + r + 8) * 64 + wn16;
            *(float2*)&up[rowA + 0 + c2] = make_float2(accA[0][0], accA[0][1]);
            *(float2*)&up[rowA + 8 + c2] = make_float2(accA[1][0], accA[1][1]);
            *(float2*)&up[rowB + 0 + c2] = make_float2(accA[0][2], accA[0][3]);
            *(float2*)&up[rowB + 8 + c2] = make_float2(accA[1][2], accA[1][3]);
        }
        __syncthreads();

        // pair-sum kg halves, pack bf16, scatter to all ranks
        {
            const float* up = (const float*)(smraw + L_OFF_UPART);
            float v0 = up[r_e * 64 + pe + 0] + up[(16 + r_e) * 64 + pe + 0];
            float v1 = up[r_e * 64 + pe + 1] + up[(16 + r_e) * 64 + pe + 1];
            float v2 = up[r_e * 64 + pe + 2] + up[(16 + r_e) * 64 + pe + 2];
            float v3 = up[r_e * 64 + pe + 3] + up[(16 + r_e) * 64 + pe + 3];
            uint2 pk;
            __nv_bfloat162 b01 = __floats2bfloat162_rn(v0, v1);
            __nv_bfloat162 b23 = __floats2bfloat162_rn(v2, v3);
            pk.x = *(uint32_t*)&b01;
            pk.y = *(uint32_t*)&b23;
            const int moff = ((buf * CLUSTER_N + rank) * 16 + r_e) * 128 + pe * 2;
            #pragma unroll
            for (int rk = 0; rk < CLUSTER_N; rk++)
                *(uint2*)(peerMb[rk] + moff) = pk;
        }
        // poll next timestep's producer flag while peers arrive at the barrier
        if (tid == 0 && t + 1 < T_STEPS) {
            volatile unsigned int* f = &g_tdone[t + 1];
            while (*f < TILES_PER_T) {}
            __threadfence();
        }
        cl.sync();

        // prefetch Iin[t+1] (hidden under reduce + phase B)
        if (t + 1 < T_STEPS) {
            const __half* p1 = &g_Iin[(size_t)(t + 1) * BATCH * HID + iinOff];
            #pragma unroll
            for (int nb = 0; nb < 2; nb++)
                #pragma unroll
                for (int sub = 0; sub < 2; sub++) {
                    iinn[nb * 2 + sub]     = __ldcs((const uint32_t*)(p1 + nb * 16 + sub * 8));
                    iinn[4 + nb * 2 + sub] = __ldcs((const uint32_t*)(p1 + 8 * HID + nb * 16 + sub * 8));
                }
        }

        // reduce 4 ranks -> U bf16 tile
        {
            float s0 = 0.f, s1 = 0.f, s2 = 0.f, s3 = 0.f;
            #pragma unroll
            for (int rk = 0; rk < CLUSTER_N; rk++) {
                uint2 q = *(uint2*)(mboxLocal + ((buf * CLUSTER_N + rk) * 16 + r_e) * 128 + pe * 2);
                float2 f01 = __bfloat1622float2(*(__nv_bfloat162*)&q.x);
                float2 f23 = __bfloat1622float2(*(__nv_bfloat162*)&q.y);
                s0 += f01.x; s1 += f01.y; s2 += f23.x; s3 += f23.y;
            }
            uint2 pk;
            __nv_bfloat162 b01 = __floats2bfloat162_rn(s0, s1);
            __nv_bfloat162 b23 = __floats2bfloat162_rn(s2, s3);
            pk.x = *(uint32_t*)&b01;
            pk.y = *(uint32_t*)&b23;
            *(uint2*)(smraw + L_OFF_U + SWZ128(r_e * 128 + pe * 2)) = pk;
        }
        __syncthreads();

        // ---- phase B ----
        float accB[2][2][4];
        #pragma unroll
        for (int nb = 0; nb < 2; nb++)
            #pragma unroll
            for (int sub = 0; sub < 2; sub++)
                #pragma unroll
                for (int q = 0; q < 4; q++) accB[nb][sub][q] = 0.f;

        const uint32_t uB = sb + L_OFF_U;
        const uint32_t wB = sb + L_OFF_WPL;
        #pragma unroll
        for (int ks = 0; ks < 4; ks++) {
            const int kb = ks * 32;
            uint32_t af[4];
            ldm_x4(af, uB + SWZ128(aRow * 128 + kb + aCol));
            #pragma unroll
            for (int nb = 0; nb < 2; nb++) {
                uint32_t bf[4];
                ldm_x4(bf, wB + SWZ128((wid * 32 + nb * 16 + bRow) * 128 + kb + bCol));
                mma_bf16(accB[nb][0], af, bf[0], bf[1]);
                mma_bf16(accB[nb][1], af, bf[2], bf[3]);
            }
        }

        #pragma unroll
        for (int nb = 0; nb < 2; nb++) {
            #pragma unroll
            for (int sub = 0; sub < 2; sub++) {
                const int j  = nb * 2 + sub;
                const int hc = wid * 32 + nb * 16 + sub * 8 + c2;
                const uint32_t thBase = (uint32_t)(L_OFF_TH + (hc >> 6) * 2048);
                {
                    float2 iv = __half22float2(*(__half2*)&iinc[j]);
                    float m0 = (iv.x + accB[nb][sub][0] - memv[j].x) * ALPHA;
                    float m1 = (iv.y + accB[nb][sub][1] - memv[j].y) * ALPHA;
                    memv[j].x = m0;  memv[j].y = m1;
                    float tv0 = tanhf(m0), tv1 = tanhf(m1);
                    rmv[j].x = fmaxf(rmv[j].x, tv0);
                    rmv[j].y = fmaxf(rmv[j].y, tv1);
                    *(__nv_bfloat162*)(smraw + thBase + SWZ128(r * 128 + (hc & 63) * 2)) =
                        __floats2bfloat162_rn(tv0, tv1);
                }
                {
                    float2 iv = __half22float2(*(__half2*)&iinc[4 + j]);
                    float m0 = (iv.x + accB[nb][sub][2] - memv[4 + j].x) * ALPHA;
                    float m1 = (iv.y + accB[nb][sub][3] - memv[4 + j].y) * ALPHA;
                    memv[4 + j].x = m0;  memv[4 + j].y = m1;
                    float tv0 = tanhf(m0), tv1 = tanhf(m1);
                    rmv[4 + j].x = fmaxf(rmv[4 + j].x, tv0);
                    rmv[4 + j].y = fmaxf(rmv[4 + j].y, tv1);
                    *(__nv_bfloat162*)(smraw + thBase + SWZ128((r + 8) * 128 + (hc & 63) * 2)) =
                        __floats2bfloat162_rn(tv0, tv1);
                }
            }
        }

        // rotate Iin pipeline
        #pragma unroll
        for (int q = 0; q < 8; q++) iinc[q] = iinn[q];
    }

    // ---- fused readout partials: logits[b][o] += sum_h rm[b][h] * Wout[o][h] ----
    float pr0[OUTD], pr1[OUTD];
    #pragma unroll
    for (int o = 0; o < OUTD; o++) { pr0[o] = 0.f; pr1[o] = 0.f; }
    #pragma unroll
    for (int nb = 0; nb < 2; nb++)
        #pragma unroll
        for (int sub = 0; sub < 2; sub++) {
            const int j  = nb * 2 + sub;
            const int hc = wid * 32 + nb * 16 + sub * 8 + c2;
            #pragma unroll
            for (int o = 0; o < OUTD; o++) {
                float2 wv = *(const float2*)&Wout[(size_t)o * HID + H0 + hc];
                pr0[o] = fmaf(rmv[j].x,     wv.x, fmaf(rmv[j].y,     wv.y, pr0[o]));
                pr1[o] = fmaf(rmv[4 + j].x, wv.x, fmaf(rmv[4 + j].y, wv.y, pr1[o]));
            }
        }
    #pragma unroll
    for (int o = 0; o < OUTD; o++) {
        pr0[o] += __shfl_xor_sync(0xffffffffu, pr0[o], 1);
        pr0[o] += __shfl_xor_sync(0xffffffffu, pr0[o], 2);
        pr1[o] += __shfl_xor_sync(0xffffffffu, pr1[o], 1);
        pr1[o] += __shfl_xor_sync(0xffffffffu, pr1[o], 2);
    }
    __syncthreads();   // UPART reads done; reuse as wred[8][16][12]
    float* wred = (float*)(smraw + L_OFF_UPART);
    if ((lane & 3) == 0) {
        #pragma unroll
        for (int o = 0; o < OUTD; o++) {
            wred[(wid * 16 + r)     * 12 + o] = pr0[o];
            wred[(wid * 16 + r + 8) * 12 + o] = pr1[o];
        }
    }
    __syncthreads();
    if (tid < ROWS_PER_CL * OUTD) {
        int row = tid / OUTD;
        int o   = tid % OUTD;
        float s = 0.f;
        #pragma unroll
        for (int w = 0; w < 8; w++) s += wred[(w * 16 + row) * 12 + o];
        atomicAdd(&g_logits[(b0 + row) * OUTD + o], s);
    }
    cl.sync();   // no CTA exits while peer DSMEM traffic could be in flight
}

// ---------------- fused heterogeneous kernel ----------------
__global__ void __cluster_dims__(CLUSTER_N, 1, 1) __launch_bounds__(256, 2)
fused_kernel(const float* __restrict__ pin, const float* __restrict__ pout,
             const float* __restrict__ l, const float* __restrict__ Wout) {
    extern __shared__ char smraw[];
    const int bid = blockIdx.x;
    if (bid < NCTAS_LOOP) {
        loop_role(smraw, bid, pin, pout, l, Wout);
    } else {
        gemm_role(smraw, bid - NCTAS_LOOP);
    }
}

// ---------------- softmax kernel (tiny) ----------------
__global__ __launch_bounds__(BATCH) void softmax_kernel(float* __restrict__ out) {
    const int b = threadIdx.x;
    float v[OUTD];
    #pragma unroll
    for (int o = 0; o < OUTD; o++) v[o] = g_logits[b * OUTD + o];
    float mx = v[0];
    #pragma unroll
    for (int o = 1; o < OUTD; o++) mx = fmaxf(mx, v[o]);
    float e[OUTD], sum = 0.0f;
    #pragma unroll
    for (int o = 0; o < OUTD; o++) { e[o] = expf(v[o] - mx); sum += e[o]; }
    float inv = 1.0f / sum;
    #pragma unroll
    for (int o = 0; o < OUTD; o++) out[b * OUTD + o] = e[o] * inv;
}

// ---------------- launch ----------------
extern "C" void kernel_launch(void* const* d_in, const int* in_sizes, int n_in,
                              void* d_out, int out_size) {
    const float* spk  = (const float*)d_in[0];
    const float* Win  = (const float*)d_in[1];
    const float* Wout = (const float*)d_in[2];
    const float* pin  = (const float*)d_in[3];
    const float* pout = (const float*)d_in[4];
    const float* l    = (const float*)d_in[5];
    float* out = (float*)d_out;

    static bool init = false;
    if (!init) {
        cudaFuncSetAttribute(fused_kernel, cudaFuncAttributeMaxDynamicSharedMemorySize, FUSED_SMEM);
        init = true;
    }

    prep_kernel<<<PREP_BLKS, 256>>>(spk, Win);
    fused_kernel<<<NCTAS_ALL, 256, FUSED_SMEM>>>(pin, pout, l, Wout);
    softmax_kernel<<<1, BATCH>>>(out);
}

// round 16
// speedup vs baseline: 1.3262x; 1.0108x over previous
#include <cuda_runtime.h>
#include <cuda_bf16.h>
#include <cuda_fp16.h>
#include <cooperative_groups.h>
#include <math.h>
#include <stdint.h>

namespace cg = cooperative_groups;

#define T_STEPS 100
#define BATCH   256
#define IN_DIM  784
#define HID     1024
#define OUTD    10
#define P_DIM   64
#define ALPHA   0.05f   // DT / TAUM

#define M_TOT   (T_STEPS * BATCH)   // 25600
#define K_PAD   832                 // 13 * 64 fp16 (128B rows)
#define N_CHUNK 13
#define TILES_PER_T 16

#define NCTAS_LOOP 64
#define NCTAS_GEMM 1600
#define NCTAS_ALL  (NCTAS_LOOP + NCTAS_GEMM)

#define PREP_WIN_BLKS 416           // HID*104/256
#define PREP_SPK_BLKS 10400         // M_TOT*104/256
#define PREP_BLKS     (PREP_WIN_BLKS + PREP_SPK_BLKS)

// ---------------- scratch (static device globals) ----------------
__device__ __half g_Iin[(size_t)T_STEPS * BATCH * HID];   // fp16 input currents
__device__ float  g_logits[BATCH * OUTD];
__device__ __half g_spkh[(size_t)M_TOT * K_PAD];
__device__ __half g_WinH[(size_t)HID * K_PAD];
__device__ unsigned int g_tdone[T_STEPS];

// ---------------- helpers ----------------
__device__ __forceinline__ uint32_t smem_u32(const void* p) {
    uint32_t a;
    asm("{ .reg .u64 t; cvta.to.shared.u64 t, %1; cvt.u32.u64 %0, t; }" : "=r"(a) : "l"(p));
    return a;
}
#define SWZ128(o) ((o) ^ (((o) >> 3) & 0x70))
#define CP_COMMIT() asm volatile("cp.async.commit_group;" ::: "memory")
#define CP_WAIT(n)  asm volatile("cp.async.wait_group %0;" :: "n"(n) : "memory")

__device__ __forceinline__ void ldm_x4(uint32_t* r, uint32_t addr) {
    asm volatile("ldmatrix.sync.aligned.m8n8.x4.shared.b16 {%0,%1,%2,%3}, [%4];"
                 : "=r"(r[0]), "=r"(r[1]), "=r"(r[2]), "=r"(r[3]) : "r"(addr));
}
__device__ __forceinline__ void mma_bf16(float* c, const uint32_t* a, uint32_t b0, uint32_t b1) {
    asm volatile("mma.sync.aligned.m16n8k16.row.col.f32.bf16.bf16.f32 "
                 "{%0,%1,%2,%3}, {%4,%5,%6,%7}, {%8,%9}, {%0,%1,%2,%3};"
                 : "+f"(c[0]), "+f"(c[1]), "+f"(c[2]), "+f"(c[3])
                 : "r"(a[0]), "r"(a[1]), "r"(a[2]), "r"(a[3]), "r"(b0), "r"(b1));
}
__device__ __forceinline__ void mma_f16(float* c, const uint32_t* a, uint32_t b0, uint32_t b1) {
    asm volatile("mma.sync.aligned.m16n8k16.row.col.f32.f16.f16.f32 "
                 "{%0,%1,%2,%3}, {%4,%5,%6,%7}, {%8,%9}, {%0,%1,%2,%3};"
                 : "+f"(c[0]), "+f"(c[1]), "+f"(c[2]), "+f"(c[3])
                 : "r"(a[0]), "r"(a[1]), "r"(a[2]), "r"(a[3]), "r"(b0), "r"(b1));
}
// fast tanh: 1 - 2/(1+e^{2x}); correct limits at +/-inf, rel err ~1e-6
__device__ __forceinline__ float tanh_fast(float x) {
    float e = __expf(2.0f * x);
    return 1.0f - __fdividef(2.0f, 1.0f + e);
}

// ---------------- merged prep kernel (verified 18us, DRAM-bound) ----------------
__global__ void prep_kernel(const float* __restrict__ spk, const float* __restrict__ Win) {
    const int blk = blockIdx.x;
    const int tid = threadIdx.x;
    if (blk == 0 && tid < T_STEPS) g_tdone[tid] = 0u;
    if (blk < 10 && blk * 256 + tid < BATCH * OUTD) g_logits[blk * 256 + tid] = 0.0f;

    if (blk < PREP_WIN_BLKS) {
        int i   = blk * 256 + tid;
        int row = i / (K_PAD / 8);
        int c0  = (i % (K_PAD / 8)) * 8;
        __half v[8];
        if (c0 < IN_DIM) {
            const float4* src = (const float4*)&Win[(size_t)row * IN_DIM + c0];
            float4 f0 = src[0], f1 = src[1];
            v[0] = __float2half_rn(f0.x); v[1] = __float2half_rn(f0.y);
            v[2] = __float2half_rn(f0.z); v[3] = __float2half_rn(f0.w);
            v[4] = __float2half_rn(f1.x); v[5] = __float2half_rn(f1.y);
            v[6] = __float2half_rn(f1.z); v[7] = __float2half_rn(f1.w);
        } else {
            #pragma unroll
            for (int j = 0; j < 8; j++) v[j] = __float2half_rn(0.0f);
        }
        *(uint4*)&g_WinH[(size_t)row * K_PAD + c0] = *(uint4*)v;
    } else {
        int i   = (blk - PREP_WIN_BLKS) * 256 + tid;
        int row = i / (K_PAD / 8);
        int c0  = (i % (K_PAD / 8)) * 8;
        __half v[8];
        if (c0 < IN_DIM) {
            const float4* src = (const float4*)&spk[(size_t)row * IN_DIM + c0];
            float4 f0 = src[0], f1 = src[1];
            v[0] = __float2half_rn(f0.x); v[1] = __float2half_rn(f0.y);
            v[2] = __float2half_rn(f0.z); v[3] = __float2half_rn(f0.w);
            v[4] = __float2half_rn(f1.x); v[5] = __float2half_rn(f1.y);
            v[6] = __float2half_rn(f1.z); v[7] = __float2half_rn(f1.w);
        } else {
            #pragma unroll
            for (int j = 0; j < 8; j++) v[j] = __float2half_rn(0.0f);
        }
        *(uint4*)&g_spkh[(size_t)row * K_PAD + c0] = *(uint4*)v;
    }
}

// ---------------- gemm role (fp16, 3-stage cp.async pipeline) ----------------
#define TILE_BYTES  16384
#define STAGE_BYTES (2 * TILE_BYTES)
#define GEMM_SMEM   (3 * STAGE_BYTES)   // 98304, 3 stages

__device__ __forceinline__ void copy_tile(uint32_t sdst, const __half* __restrict__ g,
                                          int row0, int k0, int tid) {
    #pragma unroll
    for (int j = 0; j < 4; j++) {
        int i   = tid + j * 256;
        int row = i >> 3;
        int cb  = i & 7;
        const void* gp = g + (size_t)(row0 + row) * K_PAD + k0 + cb * 8;
        uint32_t so = sdst + SWZ128(row * 128 + cb * 16);
        asm volatile("cp.async.cg.shared.global [%0], [%1], 16;" :: "r"(so), "l"(gp));
    }
}

__device__ void gemm_role(char* smraw, int gid) {
    const uint32_t sb  = smem_u32(smraw);
    const int tid  = threadIdx.x;
    const int wid  = tid >> 5;
    const int lane = tid & 31;
    const int m0 = (gid >> 3) * 128;
    const int n0 = (gid & 7) * 128;
    const int wm = (wid & 3) * 32;
    const int wn = (wid >> 2) * 64;

    const uint32_t stA[3] = {sb, sb + STAGE_BYTES, sb + 2 * STAGE_BYTES};
    const uint32_t stB[3] = {stA[0] + TILE_BYTES, stA[1] + TILE_BYTES, stA[2] + TILE_BYTES};

    float acc[2][8][4];
    #pragma unroll
    for (int mi = 0; mi < 2; mi++)
        #pragma unroll
        for (int nj = 0; nj < 8; nj++)
            #pragma unroll
            for (int q = 0; q < 4; q++) acc[mi][nj][q] = 0.0f;

    // prologue: chunks 0,1,2
    #pragma unroll
    for (int p = 0; p < 3; p++) {
        copy_tile(stA[p], g_spkh, m0, p * 64, tid);
        copy_tile(stB[p], g_WinH, n0, p * 64, tid);
        CP_COMMIT();
    }

    const int arow = wm + (lane & 15);
    const int acolL = (lane >> 4) << 4;
    const int brow = (lane & 7) + ((lane >> 4) << 3);
    const int bcolL = ((lane >> 3) & 1) << 4;

    for (int k = 0; k < N_CHUNK; k++) {
        const int s = k % 3;
        if (k < N_CHUNK - 1) CP_WAIT(2); else CP_WAIT(0);
        __syncthreads();

        #pragma unroll
        for (int ks = 0; ks < 4; ks++) {
            const int kb = ks * 32;
            uint32_t af[2][4];
            ldm_x4(af[0], stA[s] + SWZ128((arow)      * 128 + kb + acolL));
            ldm_x4(af[1], stA[s] + SWZ128((arow + 16) * 128 + kb + acolL));

            #pragma unroll
            for (int nb = 0; nb < 4; nb++) {
                const uint32_t boff = SWZ128((wn + nb * 16 + brow) * 128 + kb + bcolL);
                uint32_t bh[4];
                ldm_x4(bh, stB[s] + boff);
                #pragma unroll
                for (int mi = 0; mi < 2; mi++) {
                    mma_f16(acc[mi][nb * 2 + 0], af[mi], bh[0], bh[1]);
                    mma_f16(acc[mi][nb * 2 + 1], af[mi], bh[2], bh[3]);
                }
            }
        }
        __syncthreads();

        if (k + 3 < N_CHUNK) {
            const int k0 = (k + 3) * 64;
            copy_tile(stA[s], g_spkh, m0, k0, tid);
            copy_tile(stB[s], g_WinH, n0, k0, tid);
            CP_COMMIT();
        }
    }

    const int r0 = lane >> 2;
    const int c0 = (lane & 3) * 2;
    #pragma unroll
    for (int mi = 0; mi < 2; mi++) {
        #pragma unroll
        for (int nj = 0; nj < 8; nj++) {
            const int row = m0 + wm + mi * 16 + r0;
            const int col = n0 + wn + nj * 8 + c0;
            __half2 v01 = __floats2half2_rn(acc[mi][nj][0], acc[mi][nj][1]);
            __half2 v23 = __floats2half2_rn(acc[mi][nj][2], acc[mi][nj][3]);
            *(__half2*)&g_Iin[(size_t)row * HID + col]       = v01;
            *(__half2*)&g_Iin[(size_t)(row + 8) * HID + col] = v23;
        }
    }

    __syncthreads();
    if (tid == 0) {
        __threadfence();
        atomicAdd(&g_tdone[gid >> 4], 1u);
    }
}

// ---------------- loop role: pipelined Iin prefetch + fast tanh ----------------
#define CLUSTER_N   4
#define ROWS_PER_CL 16
#define H_PER_CTA   256

#define L_OFF_POUT  0        // 32KB
#define L_OFF_WPL   32768    // 32KB
#define L_OFF_TH    65536    // 8KB
#define L_OFF_U     73728    // 2KB
#define L_OFF_UPART 75776    // 8KB (reused as wred at end)
#define L_OFF_MBOX  83968    // 16KB
#define LOOP_SMEM   100352

#define FUSED_SMEM  (LOOP_SMEM > GEMM_SMEM ? LOOP_SMEM : GEMM_SMEM)

__device__ void loop_role(char* smraw, int bid,
                          const float* __restrict__ pin, const float* __restrict__ pout,
                          const float* __restrict__ l, const float* __restrict__ Wout) {
    const uint32_t sb = smem_u32(smraw);

    cg::cluster_group cl = cg::this_cluster();
    const int rank = cl.block_rank();
    const int cidx = bid / CLUSTER_N;
    const int b0   = cidx * ROWS_PER_CL;
    const int H0   = rank * H_PER_CTA;
    const int tid  = threadIdx.x;
    const int wid  = tid >> 5;
    const int lane = tid & 31;

    for (int i = tid; i < H_PER_CTA * P_DIM; i += 256) {
        int hl = i >> 6;
        int p  = i & 63;
        float pv = pout[(size_t)(H0 + hl) * P_DIM + p];
        *(__nv_bfloat16*)(smraw + L_OFF_POUT + (hl >> 6) * 8192
                          + SWZ128(p * 128 + (hl & 63) * 2)) = __float2bfloat16(pv);
        float wv = pin[(size_t)(H0 + hl) * P_DIM + p] * l[p];
        *(__nv_bfloat16*)(smraw + L_OFF_WPL + SWZ128(hl * 128 + p * 2)) = __float2bfloat16(wv);
    }
    for (int i = tid; i < (8192 + 2048) / 4; i += 256)
        ((uint32_t*)(smraw + L_OFF_TH))[i] = 0;

    const int kg   = wid >> 2;
    const int wn16 = (wid & 3) * 16;
    const int aRow = lane & 15;
    const int aCol = (lane >> 4) << 4;
    const int bRow = (lane & 7) + ((lane >> 4) << 3);
    const int bCol = ((lane >> 3) & 1) << 4;
    const int r    = lane >> 2;
    const int c2   = (lane & 3) * 2;

    const int r_e  = tid >> 4;
    const int pe   = (tid & 15) * 4;
    char* mboxLocal = smraw + L_OFF_MBOX;
    char* peerMb[CLUSTER_N];
    #pragma unroll
    for (int rk = 0; rk < CLUSTER_N; rk++)
        peerMb[rk] = (char*)cl.map_shared_rank((void*)mboxLocal, rk);

    float2 memv[8], rmv[8];
    #pragma unroll
    for (int j = 0; j < 8; j++) { memv[j] = make_float2(0.f, 0.f); rmv[j] = make_float2(-2.f, -2.f); }

    const size_t iinOff = ((size_t)(b0 + r)) * HID + H0 + wid * 32 + c2;

    if (tid == 0) {
        volatile unsigned int* f = &g_tdone[0];
        while (*f < TILES_PER_T) {}
        __threadfence();
    }
    cl.sync();

    uint32_t iinc[8], iinn[8];
    {
        const __half* p0 = &g_Iin[iinOff];
        #pragma unroll
        for (int nb = 0; nb < 2; nb++)
            #pragma unroll
            for (int sub = 0; sub < 2; sub++) {
                iinc[nb * 2 + sub]     = __ldcs((const uint32_t*)(p0 + nb * 16 + sub * 8));
                iinc[4 + nb * 2 + sub] = __ldcs((const uint32_t*)(p0 + 8 * HID + nb * 16 + sub * 8));
            }
    }

    for (int t = 0; t < T_STEPS; t++) {
        __syncthreads();
        const int buf = t & 1;

        // ---- phase A ----
        float accA[2][4] = {{0.f,0.f,0.f,0.f},{0.f,0.f,0.f,0.f}};
        #pragma unroll
        for (int cc = 0; cc < 2; cc++) {
            const int ch = kg * 2 + cc;
            const uint32_t thB = sb + L_OFF_TH + ch * 2048;
            const uint32_t poB = sb + L_OFF_POUT + ch * 8192;
            #pragma unroll
            for (int ks = 0; ks < 4; ks++) {
                const int kb = ks * 32;
                uint32_t af[4], bf[4];
                ldm_x4(af, thB + SWZ128(aRow * 128 + kb + aCol));
                ldm_x4(bf, poB + SWZ128((wn16 + bRow) * 128 + kb + bCol));
                mma_bf16(accA[0], af, bf[0], bf[1]);
                mma_bf16(accA[1], af, bf[2], bf[3]);
            }
        }
        {
            float* up = (float*)(smraw + L_OFF_UPART);
            const int rowA = (kg * 16 + r) * 64 + wn16;
            const int rowB = (kg * 16 + r + 8) * 64 + wn16;
            *(float2*)&up[rowA + 0 + c2] = make_float2(accA[0][0], accA[0][1]);
            *(float2*)&up[rowA + 8 + c2] = make_float2(accA[1][0], accA[1][1]);
            *(float2*)&up[rowB + 0 + c2] = make_float2(accA[0][2], accA[0][3]);
            *(float2*)&up[rowB + 8 + c2] = make_float2(accA[1][2], accA[1][3]);
        }
        __syncthreads();

        {
            const float* up = (const float*)(smraw + L_OFF_UPART);
            float v0 = up[r_e * 64 + pe + 0] + up[(16 + r_e) * 64 + pe + 0];
            float v1 = up[r_e * 64 + pe + 1] + up[(16 + r_e) * 64 + pe + 1];
            float v2 = up[r_e * 64 + pe + 2] + up[(16 + r_e) * 64 + pe + 2];
            float v3 = up[r_e * 64 + pe + 3] + up[(16 + r_e) * 64 + pe + 3];
            uint2 pk;
            __nv_bfloat162 b01 = __floats2bfloat162_rn(v0, v1);
            __nv_bfloat162 b23 = __floats2bfloat162_rn(v2, v3);
            pk.x = *(uint32_t*)&b01;
            pk.y = *(uint32_t*)&b23;
            const int moff = ((buf * CLUSTER_N + rank) * 16 + r_e) * 128 + pe * 2;
            #pragma unroll
            for (int rk = 0; rk < CLUSTER_N; rk++)
                *(uint2*)(peerMb[rk] + moff) = pk;
        }
        if (tid == 0 && t + 1 < T_STEPS) {
            volatile unsigned int* f = &g_tdone[t + 1];
            while (*f < TILES_PER_T) {}
            __threadfence();
        }
        cl.sync();

        if (t + 1 < T_STEPS) {
            const __half* p1 = &g_Iin[(size_t)(t + 1) * BATCH * HID + iinOff];
            #pragma unroll
            for (int nb = 0; nb < 2; nb++)
                #pragma unroll
                for (int sub = 0; sub < 2; sub++) {
                    iinn[nb * 2 + sub]     = __ldcs((const uint32_t*)(p1 + nb * 16 + sub * 8));
                    iinn[4 + nb * 2 + sub] = __ldcs((const uint32_t*)(p1 + 8 * HID + nb * 16 + sub * 8));
                }
        }

        {
            float s0 = 0.f, s1 = 0.f, s2 = 0.f, s3 = 0.f;
            #pragma unroll
            for (int rk = 0; rk < CLUSTER_N; rk++) {
                uint2 q = *(uint2*)(mboxLocal + ((buf * CLUSTER_N + rk) * 16 + r_e) * 128 + pe * 2);
                float2 f01 = __bfloat1622float2(*(__nv_bfloat162*)&q.x);
                float2 f23 = __bfloat1622float2(*(__nv_bfloat162*)&q.y);
                s0 += f01.x; s1 += f01.y; s2 += f23.x; s3 += f23.y;
            }
            uint2 pk;
            __nv_bfloat162 b01 = __floats2bfloat162_rn(s0, s1);
            __nv_bfloat162 b23 = __floats2bfloat162_rn(s2, s3);
            pk.x = *(uint32_t*)&b01;
            pk.y = *(uint32_t*)&b23;
            *(uint2*)(smraw + L_OFF_U + SWZ128(r_e * 128 + pe * 2)) = pk;
        }
        __syncthreads();

        // ---- phase B ----
        float accB[2][2][4];
        #pragma unroll
        for (int nb = 0; nb < 2; nb++)
            #pragma unroll
            for (int sub = 0; sub < 2; sub++)
                #pragma unroll
                for (int q = 0; q < 4; q++) accB[nb][sub][q] = 0.f;

        const uint32_t uB = sb + L_OFF_U;
        const uint32_t wB = sb + L_OFF_WPL;
        #pragma unroll
        for (int ks = 0; ks < 4; ks++) {
            const int kb = ks * 32;
            uint32_t af[4];
            ldm_x4(af, uB + SWZ128(aRow * 128 + kb + aCol));
            #pragma unroll
            for (int nb = 0; nb < 2; nb++) {
                uint32_t bf[4];
                ldm_x4(bf, wB + SWZ128((wid * 32 + nb * 16 + bRow) * 128 + kb + bCol));
                mma_bf16(accB[nb][0], af, bf[0], bf[1]);
                mma_bf16(accB[nb][1], af, bf[2], bf[3]);
            }
        }

        #pragma unroll
        for (int nb = 0; nb < 2; nb++) {
            #pragma unroll
            for (int sub = 0; sub < 2; sub++) {
                const int j  = nb * 2 + sub;
                const int hc = wid * 32 + nb * 16 + sub * 8 + c2;
                const uint32_t thBase = (uint32_t)(L_OFF_TH + (hc >> 6) * 2048);
                {
                    float2 iv = __half22float2(*(__half2*)&iinc[j]);
                    float m0 = (iv.x + accB[nb][sub][0] - memv[j].x) * ALPHA;
                    float m1 = (iv.y + accB[nb][sub][1] - memv[j].y) * ALPHA;
                    memv[j].x = m0;  memv[j].y = m1;
                    float tv0 = tanh_fast(m0), tv1 = tanh_fast(m1);
                    rmv[j].x = fmaxf(rmv[j].x, tv0);
                    rmv[j].y = fmaxf(rmv[j].y, tv1);
                    *(__nv_bfloat162*)(smraw + thBase + SWZ128(r * 128 + (hc & 63) * 2)) =
                        __floats2bfloat162_rn(tv0, tv1);
                }
                {
                    float2 iv = __half22float2(*(__half2*)&iinc[4 + j]);
                    float m0 = (iv.x + accB[nb][sub][2] - memv[4 + j].x) * ALPHA;
                    float m1 = (iv.y + accB[nb][sub][3] - memv[4 + j].y) * ALPHA;
                    memv[4 + j].x = m0;  memv[4 + j].y = m1;
                    float tv0 = tanh_fast(m0), tv1 = tanh_fast(m1);
                    rmv[4 + j].x = fmaxf(rmv[4 + j].x, tv0);
                    rmv[4 + j].y = fmaxf(rmv[4 + j].y, tv1);
                    *(__nv_bfloat162*)(smraw + thBase + SWZ128((r + 8) * 128 + (hc & 63) * 2)) =
                        __floats2bfloat162_rn(tv0, tv1);
                }
            }
        }

        #pragma unroll
        for (int q = 0; q < 8; q++) iinc[q] = iinn[q];
    }

    // ---- fused readout partials ----
    float pr0[OUTD], pr1[OUTD];
    #pragma unroll
    for (int o = 0; o < OUTD; o++) { pr0[o] = 0.f; pr1[o] = 0.f; }
    #pragma unroll
    for (int nb = 0; nb < 2; nb++)
        #pragma unroll
        for (int sub = 0; sub < 2; sub++) {
            const int j  = nb * 2 + sub;
            const int hc = wid * 32 + nb * 16 + sub * 8 + c2;
            #pragma unroll
            for (int o = 0; o < OUTD; o++) {
                float2 wv = *(const float2*)&Wout[(size_t)o * HID + H0 + hc];
                pr0[o] = fmaf(rmv[j].x,     wv.x, fmaf(rmv[j].y,     wv.y, pr0[o]));
                pr1[o] = fmaf(rmv[4 + j].x, wv.x, fmaf(rmv[4 + j].y, wv.y, pr1[o]));
            }
        }
    #pragma unroll
    for (int o = 0; o < OUTD; o++) {
        pr0[o] += __shfl_xor_sync(0xffffffffu, pr0[o], 1);
        pr0[o] += __shfl_xor_sync(0xffffffffu, pr0[o], 2);
        pr1[o] += __shfl_xor_sync(0xffffffffu, pr1[o], 1);
        pr1[o] += __shfl_xor_sync(0xffffffffu, pr1[o], 2);
    }
    __syncthreads();
    float* wred = (float*)(smraw + L_OFF_UPART);
    if ((lane & 3) == 0) {
        #pragma unroll
        for (int o = 0; o < OUTD; o++) {
            wred[(wid * 16 + r)     * 12 + o] = pr0[o];
            wred[(wid * 16 + r + 8) * 12 + o] = pr1[o];
        }
    }
    __syncthreads();
    if (tid < ROWS_PER_CL * OUTD) {
        int row = tid / OUTD;
        int o   = tid % OUTD;
        float s = 0.f;
        #pragma unroll
        for (int w = 0; w < 8; w++) s += wred[(w * 16 + row) * 12 + o];
        atomicAdd(&g_logits[(b0 + row) * OUTD + o], s);
    }
    cl.sync();
}

// ---------------- fused heterogeneous kernel ----------------
__global__ void __cluster_dims__(CLUSTER_N, 1, 1) __launch_bounds__(256, 2)
fused_kernel(const float* __restrict__ pin, const float* __restrict__ pout,
             const float* __restrict__ l, const float* __restrict__ Wout) {
    extern __shared__ char smraw[];
    const int bid = blockIdx.x;
    if (bid < NCTAS_LOOP) {
        loop_role(smraw, bid, pin, pout, l, Wout);
    } else {
        gemm_role(smraw, bid - NCTAS_LOOP);
    }
}

// ---------------- softmax kernel (tiny) ----------------
__global__ __launch_bounds__(BATCH) void softmax_kernel(float* __restrict__ out) {
    const int b = threadIdx.x;
    float v[OUTD];
    #pragma unroll
    for (int o = 0; o < OUTD; o++) v[o] = g_logits[b * OUTD + o];
    float mx = v[0];
    #pragma unroll
    for (int o = 1; o < OUTD; o++) mx = fmaxf(mx, v[o]);
    float e[OUTD], sum = 0.0f;
    #pragma unroll
    for (int o = 0; o < OUTD; o++) { e[o] = expf(v[o] - mx); sum += e[o]; }
    float inv = 1.0f / sum;
    #pragma unroll
    for (int o = 0; o < OUTD; o++) out[b * OUTD + o] = e[o] * inv;
}

// ---------------- launch ----------------
extern "C" void kernel_launch(void* const* d_in, const int* in_sizes, int n_in,
                              void* d_out, int out_size) {
    const float* spk  = (const float*)d_in[0];
    const float* Win  = (const float*)d_in[1];
    const float* Wout = (const float*)d_in[2];
    const float* pin  = (const float*)d_in[3];
    const float* pout = (const float*)d_in[4];
    const float* l    = (const float*)d_in[5];
    float* out = (float*)d_out;

    static bool init = false;
    if (!init) {
        cudaFuncSetAttribute(fused_kernel, cudaFuncAttributeMaxDynamicSharedMemorySize, FUSED_SMEM);
        init = true;
    }

    prep_kernel<<<PREP_BLKS, 256>>>(spk, Win);
    fused_kernel<<<NCTAS_ALL, 256, FUSED_SMEM>>>(pin, pout, l, Wout);
    softmax_kernel<<<1, BATCH>>>(out);
}

// round 17
// speedup vs baseline: 1.6183x; 1.2203x over previous
#include <cuda_runtime.h>
#include <cuda_bf16.h>
#include <cuda_fp16.h>
#include <cooperative_groups.h>
#include <math.h>
#include <stdint.h>

namespace cg = cooperative_groups;

#define T_STEPS 100
#define BATCH   256
#define IN_DIM  784
#define HID     1024
#define OUTD    10
#define P_DIM   64
#define ALPHA   0.05f   // DT / TAUM

#define M_TOT   (T_STEPS * BATCH)   // 25600
#define K_PAD   832                 // 13 * 64 fp16 (128B rows)
#define N_CHUNK 13
#define TILES_PER_T 16

#define NCTAS_LOOP 64
#define NCTAS_GEMM 1600

#define PREP_WIN_BLKS 416           // HID*104/256
#define PREP_SPK_BLKS 10400         // M_TOT*104/256
#define PREP_BLKS     (PREP_WIN_BLKS + PREP_SPK_BLKS)

// ---------------- scratch (static device globals) ----------------
__device__ __half g_Iin[(size_t)T_STEPS * BATCH * HID];
__device__ float  g_logits[BATCH * OUTD];
__device__ __half g_spkh[(size_t)M_TOT * K_PAD];
__device__ __half g_WinH[(size_t)HID * K_PAD];
__device__ unsigned int g_tdone[T_STEPS];

// ---------------- helpers ----------------
__device__ __forceinline__ uint32_t smem_u32(const void* p) {
    uint32_t a;
    asm("{ .reg .u64 t; cvta.to.shared.u64 t, %1; cvt.u32.u64 %0, t; }" : "=r"(a) : "l"(p));
    return a;
}
#define SWZ128(o) ((o) ^ (((o) >> 3) & 0x70))
#define CP_COMMIT() asm volatile("cp.async.commit_group;" ::: "memory")
#define CP_WAIT(n)  asm volatile("cp.async.wait_group %0;" :: "n"(n) : "memory")

__device__ __forceinline__ void ldm_x4(uint32_t* r, uint32_t addr) {
    asm volatile("ldmatrix.sync.aligned.m8n8.x4.shared.b16 {%0,%1,%2,%3}, [%4];"
                 : "=r"(r[0]), "=r"(r[1]), "=r"(r[2]), "=r"(r[3]) : "r"(addr));
}
__device__ __forceinline__ void mma_bf16(float* c, const uint32_t* a, uint32_t b0, uint32_t b1) {
    asm volatile("mma.sync.aligned.m16n8k16.row.col.f32.bf16.bf16.f32 "
                 "{%0,%1,%2,%3}, {%4,%5,%6,%7}, {%8,%9}, {%0,%1,%2,%3};"
                 : "+f"(c[0]), "+f"(c[1]), "+f"(c[2]), "+f"(c[3])
                 : "r"(a[0]), "r"(a[1]), "r"(a[2]), "r"(a[3]), "r"(b0), "r"(b1));
}
__device__ __forceinline__ void mma_f16(float* c, const uint32_t* a, uint32_t b0, uint32_t b1) {
    asm volatile("mma.sync.aligned.m16n8k16.row.col.f32.f16.f16.f32 "
                 "{%0,%1,%2,%3}, {%4,%5,%6,%7}, {%8,%9}, {%0,%1,%2,%3};"
                 : "+f"(c[0]), "+f"(c[1]), "+f"(c[2]), "+f"(c[3])
                 : "r"(a[0]), "r"(a[1]), "r"(a[2]), "r"(a[3]), "r"(b0), "r"(b1));
}
__device__ __forceinline__ float tanh_fast(float x) {
    float e = __expf(2.0f * x);
    return 1.0f - __fdividef(2.0f, 1.0f + e);
}

// ---------------- merged prep kernel (verified 18us, DRAM-bound) ----------------
__global__ void prep_kernel(const float* __restrict__ spk, const float* __restrict__ Win) {
    const int blk = blockIdx.x;
    const int tid = threadIdx.x;
    if (blk == 0 && tid < T_STEPS) g_tdone[tid] = 0u;
    if (blk < 10 && blk * 256 + tid < BATCH * OUTD) g_logits[blk * 256 + tid] = 0.0f;

    if (blk < PREP_WIN_BLKS) {
        int i   = blk * 256 + tid;
        int row = i / (K_PAD / 8);
        int c0  = (i % (K_PAD / 8)) * 8;
        __half v[8];
        if (c0 < IN_DIM) {
            const float4* src = (const float4*)&Win[(size_t)row * IN_DIM + c0];
            float4 f0 = src[0], f1 = src[1];
            v[0] = __float2half_rn(f0.x); v[1] = __float2half_rn(f0.y);
            v[2] = __float2half_rn(f0.z); v[3] = __float2half_rn(f0.w);
            v[4] = __float2half_rn(f1.x); v[5] = __float2half_rn(f1.y);
            v[6] = __float2half_rn(f1.z); v[7] = __float2half_rn(f1.w);
        } else {
            #pragma unroll
            for (int j = 0; j < 8; j++) v[j] = __float2half_rn(0.0f);
        }
        *(uint4*)&g_WinH[(size_t)row * K_PAD + c0] = *(uint4*)v;
    } else {
        int i   = (blk - PREP_WIN_BLKS) * 256 + tid;
        int row = i / (K_PAD / 8);
        int c0  = (i % (K_PAD / 8)) * 8;
        __half v[8];
        if (c0 < IN_DIM) {
            const float4* src = (const float4*)&spk[(size_t)row * IN_DIM + c0];
            float4 f0 = src[0], f1 = src[1];
            v[0] = __float2half_rn(f0.x); v[1] = __float2half_rn(f0.y);
            v[2] = __float2half_rn(f0.z); v[3] = __float2half_rn(f0.w);
            v[4] = __float2half_rn(f1.x); v[5] = __float2half_rn(f1.y);
            v[6] = __float2half_rn(f1.z); v[7] = __float2half_rn(f1.w);
        } else {
            #pragma unroll
            for (int j = 0; j < 8; j++) v[j] = __float2half_rn(0.0f);
        }
        *(uint4*)&g_spkh[(size_t)row * K_PAD + c0] = *(uint4*)v;
    }
}

// ---------------- gemm kernel (fp16, 3-stage cp.async, standalone) ----------------
#define TILE_BYTES  16384
#define STAGE_BYTES (2 * TILE_BYTES)
#define GEMM_SMEM   (3 * STAGE_BYTES)   // 98304

__device__ __forceinline__ void copy_tile(uint32_t sdst, const __half* __restrict__ g,
                                          int row0, int k0, int tid) {
    #pragma unroll
    for (int j = 0; j < 4; j++) {
        int i   = tid + j * 256;
        int row = i >> 3;
        int cb  = i & 7;
        const void* gp = g + (size_t)(row0 + row) * K_PAD + k0 + cb * 8;
        uint32_t so = sdst + SWZ128(row * 128 + cb * 16);
        asm volatile("cp.async.cg.shared.global [%0], [%1], 16;" :: "r"(so), "l"(gp));
    }
}

__global__ __launch_bounds__(256, 2) void gemm_kernel() {
    extern __shared__ char smraw[];
    const uint32_t sb  = smem_u32(smraw);
    const int gid  = blockIdx.x;
    const int tid  = threadIdx.x;
    const int wid  = tid >> 5;
    const int lane = tid & 31;
    const int m0 = (gid >> 3) * 128;     // m-tile ascending == timestep ascending
    const int n0 = (gid & 7) * 128;
    const int wm = (wid & 3) * 32;
    const int wn = (wid >> 2) * 64;

    const uint32_t stA[3] = {sb, sb + STAGE_BYTES, sb + 2 * STAGE_BYTES};
    const uint32_t stB[3] = {stA[0] + TILE_BYTES, stA[1] + TILE_BYTES, stA[2] + TILE_BYTES};

    float acc[2][8][4];
    #pragma unroll
    for (int mi = 0; mi < 2; mi++)
        #pragma unroll
        for (int nj = 0; nj < 8; nj++)
            #pragma unroll
            for (int q = 0; q < 4; q++) acc[mi][nj][q] = 0.0f;

    #pragma unroll
    for (int p = 0; p < 3; p++) {
        copy_tile(stA[p], g_spkh, m0, p * 64, tid);
        copy_tile(stB[p], g_WinH, n0, p * 64, tid);
        CP_COMMIT();
    }

    const int arow = wm + (lane & 15);
    const int acolL = (lane >> 4) << 4;
    const int brow = (lane & 7) + ((lane >> 4) << 3);
    const int bcolL = ((lane >> 3) & 1) << 4;

    for (int k = 0; k < N_CHUNK; k++) {
        const int s = k % 3;
        if (k < N_CHUNK - 1) CP_WAIT(2); else CP_WAIT(0);
        __syncthreads();

        #pragma unroll
        for (int ks = 0; ks < 4; ks++) {
            const int kb = ks * 32;
            uint32_t af[2][4];
            ldm_x4(af[0], stA[s] + SWZ128((arow)      * 128 + kb + acolL));
            ldm_x4(af[1], stA[s] + SWZ128((arow + 16) * 128 + kb + acolL));

            #pragma unroll
            for (int nb = 0; nb < 4; nb++) {
                const uint32_t boff = SWZ128((wn + nb * 16 + brow) * 128 + kb + bcolL);
                uint32_t bh[4];
                ldm_x4(bh, stB[s] + boff);
                #pragma unroll
                for (int mi = 0; mi < 2; mi++) {
                    mma_f16(acc[mi][nb * 2 + 0], af[mi], bh[0], bh[1]);
                    mma_f16(acc[mi][nb * 2 + 1], af[mi], bh[2], bh[3]);
                }
            }
        }
        __syncthreads();

        if (k + 3 < N_CHUNK) {
            const int k0 = (k + 3) * 64;
            copy_tile(stA[s], g_spkh, m0, k0, tid);
            copy_tile(stB[s], g_WinH, n0, k0, tid);
            CP_COMMIT();
        }
    }

    const int r0 = lane >> 2;
    const int c0 = (lane & 3) * 2;
    #pragma unroll
    for (int mi = 0; mi < 2; mi++) {
        #pragma unroll
        for (int nj = 0; nj < 8; nj++) {
            const int row = m0 + wm + mi * 16 + r0;
            const int col = n0 + wn + nj * 8 + c0;
            __half2 v01 = __floats2half2_rn(acc[mi][nj][0], acc[mi][nj][1]);
            __half2 v23 = __floats2half2_rn(acc[mi][nj][2], acc[mi][nj][3]);
            *(__half2*)&g_Iin[(size_t)row * HID + col]       = v01;
            *(__half2*)&g_Iin[(size_t)(row + 8) * HID + col] = v23;
        }
    }

    __syncthreads();
    if (tid == 0) {
        __threadfence();
        atomicAdd(&g_tdone[gid >> 4], 1u);
    }
}

// ---------------- loop kernel (standalone, padded smem for SM exclusivity) ----------------
#define CLUSTER_N   4
#define ROWS_PER_CL 16
#define H_PER_CTA   256

#define L_OFF_POUT  0        // 32KB
#define L_OFF_WPL   32768    // 32KB
#define L_OFF_TH    65536    // 8KB
#define L_OFF_U     73728    // 2KB
#define L_OFF_UPART 75776    // 8KB (reused as wred at end)
#define L_OFF_MBOX  83968    // 16KB
#define LOOP_SMEM_USED 100352
// Padded request: 136KB. 136+96 > 228KB SM capacity -> no gemm CTA co-resides;
// 2*136 > 228 -> exactly 1 loop CTA per SM. 64 SMs dedicated to the loop.
#define LOOP_SMEM_PAD  139264

__global__ void __cluster_dims__(CLUSTER_N, 1, 1) __launch_bounds__(256, 1)
loop_kernel(const float* __restrict__ pin, const float* __restrict__ pout,
            const float* __restrict__ l, const float* __restrict__ Wout) {
    extern __shared__ char smraw[];
    const uint32_t sb = smem_u32(smraw);

    cg::cluster_group cl = cg::this_cluster();
    const int rank = cl.block_rank();
    const int cidx = blockIdx.x / CLUSTER_N;
    const int b0   = cidx * ROWS_PER_CL;
    const int H0   = rank * H_PER_CTA;
    const int tid  = threadIdx.x;
    const int wid  = tid >> 5;
    const int lane = tid & 31;

    for (int i = tid; i < H_PER_CTA * P_DIM; i += 256) {
        int hl = i >> 6;
        int p  = i & 63;
        float pv = pout[(size_t)(H0 + hl) * P_DIM + p];
        *(__nv_bfloat16*)(smraw + L_OFF_POUT + (hl >> 6) * 8192
                          + SWZ128(p * 128 + (hl & 63) * 2)) = __float2bfloat16(pv);
        float wv = pin[(size_t)(H0 + hl) * P_DIM + p] * l[p];
        *(__nv_bfloat16*)(smraw + L_OFF_WPL + SWZ128(hl * 128 + p * 2)) = __float2bfloat16(wv);
    }
    for (int i = tid; i < (8192 + 2048) / 4; i += 256)
        ((uint32_t*)(smraw + L_OFF_TH))[i] = 0;

    const int kg   = wid >> 2;
    const int wn16 = (wid & 3) * 16;
    const int aRow = lane & 15;
    const int aCol = (lane >> 4) << 4;
    const int bRow = (lane & 7) + ((lane >> 4) << 3);
    const int bCol = ((lane >> 3) & 1) << 4;
    const int r    = lane >> 2;
    const int c2   = (lane & 3) * 2;

    const int r_e  = tid >> 4;
    const int pe   = (tid & 15) * 4;
    char* mboxLocal = smraw + L_OFF_MBOX;
    char* peerMb[CLUSTER_N];
    #pragma unroll
    for (int rk = 0; rk < CLUSTER_N; rk++)
        peerMb[rk] = (char*)cl.map_shared_rank((void*)mboxLocal, rk);

    float2 memv[8], rmv[8];
    #pragma unroll
    for (int j = 0; j < 8; j++) { memv[j] = make_float2(0.f, 0.f); rmv[j] = make_float2(-2.f, -2.f); }

    const size_t iinOff = ((size_t)(b0 + r)) * HID + H0 + wid * 32 + c2;

    if (tid == 0) {
        volatile unsigned int* f = &g_tdone[0];
        while (*f < TILES_PER_T) {}
        __threadfence();
    }
    cl.sync();

    uint32_t iinc[8], iinn[8];
    {
        const __half* p0 = &g_Iin[iinOff];
        #pragma unroll
        for (int nb = 0; nb < 2; nb++)
            #pragma unroll
            for (int sub = 0; sub < 2; sub++) {
                iinc[nb * 2 + sub]     = __ldcs((const uint32_t*)(p0 + nb * 16 + sub * 8));
                iinc[4 + nb * 2 + sub] = __ldcs((const uint32_t*)(p0 + 8 * HID + nb * 16 + sub * 8));
            }
    }

    for (int t = 0; t < T_STEPS; t++) {
        __syncthreads();
        const int buf = t & 1;

        // ---- phase A ----
        float accA[2][4] = {{0.f,0.f,0.f,0.f},{0.f,0.f,0.f,0.f}};
        #pragma unroll
        for (int cc = 0; cc < 2; cc++) {
            const int ch = kg * 2 + cc;
            const uint32_t thB = sb + L_OFF_TH + ch * 2048;
            const uint32_t poB = sb + L_OFF_POUT + ch * 8192;
            #pragma unroll
            for (int ks = 0; ks < 4; ks++) {
                const int kb = ks * 32;
                uint32_t af[4], bf[4];
                ldm_x4(af, thB + SWZ128(aRow * 128 + kb + aCol));
                ldm_x4(bf, poB + SWZ128((wn16 + bRow) * 128 + kb + bCol));
                mma_bf16(accA[0], af, bf[0], bf[1]);
                mma_bf16(accA[1], af, bf[2], bf[3]);
            }
        }
        {
            float* up = (float*)(smraw + L_OFF_UPART);
            const int rowA = (kg * 16 + r) * 64 + wn16;
            const int rowB = (kg * 16 + r + 8) * 64 + wn16;
            *(float2*)&up[rowA + 0 + c2] = make_float2(accA[0][0], accA[0][1]);
            *(float2*)&up[rowA + 8 + c2] = make_float2(accA[1][0], accA[1][1]);
            *(float2*)&up[rowB + 0 + c2] = make_float2(accA[0][2], accA[0][3]);
            *(float2*)&up[rowB + 8 + c2] = make_float2(accA[1][2], accA[1][3]);
        }
        __syncthreads();

        {
            const float* up = (const float*)(smraw + L_OFF_UPART);
            float v0 = up[r_e * 64 + pe + 0] + up[(16 + r_e) * 64 + pe + 0];
            float v1 = up[r_e * 64 + pe + 1] + up[(16 + r_e) * 64 + pe + 1];
            float v2 = up[r_e * 64 + pe + 2] + up[(16 + r_e) * 64 + pe + 2];
            float v3 = up[r_e * 64 + pe + 3] + up[(16 + r_e) * 64 + pe + 3];
            uint2 pk;
            __nv_bfloat162 b01 = __floats2bfloat162_rn(v0, v1);
            __nv_bfloat162 b23 = __floats2bfloat162_rn(v2, v3);
            pk.x = *(uint32_t*)&b01;
            pk.y = *(uint32_t*)&b23;
            const int moff = ((buf * CLUSTER_N + rank) * 16 + r_e) * 128 + pe * 2;
            #pragma unroll
            for (int rk = 0; rk < CLUSTER_N; rk++)
                *(uint2*)(peerMb[rk] + moff) = pk;
        }
        if (tid == 0 && t + 1 < T_STEPS) {
            volatile unsigned int* f = &g_tdone[t + 1];
            while (*f < TILES_PER_T) {}
            __threadfence();
        }
        cl.sync();

        if (t + 1 < T_STEPS) {
            const __half* p1 = &g_Iin[(size_t)(t + 1) * BATCH * HID + iinOff];
            #pragma unroll
            for (int nb = 0; nb < 2; nb++)
                #pragma unroll
                for (int sub = 0; sub < 2; sub++) {
                    iinn[nb * 2 + sub]     = __ldcs((const uint32_t*)(p1 + nb * 16 + sub * 8));
                    iinn[4 + nb * 2 + sub] = __ldcs((const uint32_t*)(p1 + 8 * HID + nb * 16 + sub * 8));
                }
        }

        {
            float s0 = 0.f, s1 = 0.f, s2 = 0.f, s3 = 0.f;
            #pragma unroll
            for (int rk = 0; rk < CLUSTER_N; rk++) {
                uint2 q = *(uint2*)(mboxLocal + ((buf * CLUSTER_N + rk) * 16 + r_e) * 128 + pe * 2);
                float2 f01 = __bfloat1622float2(*(__nv_bfloat162*)&q.x);
                float2 f23 = __bfloat1622float2(*(__nv_bfloat162*)&q.y);
                s0 += f01.x; s1 += f01.y; s2 += f23.x; s3 += f23.y;
            }
            uint2 pk;
            __nv_bfloat162 b01 = __floats2bfloat162_rn(s0, s1);
            __nv_bfloat162 b23 = __floats2bfloat162_rn(s2, s3);
            pk.x = *(uint32_t*)&b01;
            pk.y = *(uint32_t*)&b23;
            *(uint2*)(smraw + L_OFF_U + SWZ128(r_e * 128 + pe * 2)) = pk;
        }
        __syncthreads();

        // ---- phase B ----
        float accB[2][2][4];
        #pragma unroll
        for (int nb = 0; nb < 2; nb++)
            #pragma unroll
            for (int sub = 0; sub < 2; sub++)
                #pragma unroll
                for (int q = 0; q < 4; q++) accB[nb][sub][q] = 0.f;

        const uint32_t uB = sb + L_OFF_U;
        const uint32_t wB = sb + L_OFF_WPL;
        #pragma unroll
        for (int ks = 0; ks < 4; ks++) {
            const int kb = ks * 32;
            uint32_t af[4];
            ldm_x4(af, uB + SWZ128(aRow * 128 + kb + aCol));
            #pragma unroll
            for (int nb = 0; nb < 2; nb++) {
                uint32_t bf[4];
                ldm_x4(bf, wB + SWZ128((wid * 32 + nb * 16 + bRow) * 128 + kb + bCol));
                mma_bf16(accB[nb][0], af, bf[0], bf[1]);
                mma_bf16(accB[nb][1], af, bf[2], bf[3]);
            }
        }

        #pragma unroll
        for (int nb = 0; nb < 2; nb++) {
            #pragma unroll
            for (int sub = 0; sub < 2; sub++) {
                const int j  = nb * 2 + sub;
                const int hc = wid * 32 + nb * 16 + sub * 8 + c2;
                const uint32_t thBase = (uint32_t)(L_OFF_TH + (hc >> 6) * 2048);
                {
                    float2 iv = __half22float2(*(__half2*)&iinc[j]);
                    float m0 = (iv.x + accB[nb][sub][0] - memv[j].x) * ALPHA;
                    float m1 = (iv.y + accB[nb][sub][1] - memv[j].y) * ALPHA;
                    memv[j].x = m0;  memv[j].y = m1;
                    float tv0 = tanh_fast(m0), tv1 = tanh_fast(m1);
                    rmv[j].x = fmaxf(rmv[j].x, tv0);
                    rmv[j].y = fmaxf(rmv[j].y, tv1);
                    *(__nv_bfloat162*)(smraw + thBase + SWZ128(r * 128 + (hc & 63) * 2)) =
                        __floats2bfloat162_rn(tv0, tv1);
                }
                {
                    float2 iv = __half22float2(*(__half2*)&iinc[4 + j]);
                    float m0 = (iv.x + accB[nb][sub][2] - memv[4 + j].x) * ALPHA;
                    float m1 = (iv.y + accB[nb][sub][3] - memv[4 + j].y) * ALPHA;
                    memv[4 + j].x = m0;  memv[4 + j].y = m1;
                    float tv0 = tanh_fast(m0), tv1 = tanh_fast(m1);
                    rmv[4 + j].x = fmaxf(rmv[4 + j].x, tv0);
                    rmv[4 + j].y = fmaxf(rmv[4 + j].y, tv1);
                    *(__nv_bfloat162*)(smraw + thBase + SWZ128((r + 8) * 128 + (hc & 63) * 2)) =
                        __floats2bfloat162_rn(tv0, tv1);
                }
            }
        }

        #pragma unroll
        for (int q = 0; q < 8; q++) iinc[q] = iinn[q];
    }

    // ---- fused readout partials ----
    float pr0[OUTD], pr1[OUTD];
    #pragma unroll
    for (int o = 0; o < OUTD; o++) { pr0[o] = 0.f; pr1[o] = 0.f; }
    #pragma unroll
    for (int nb = 0; nb < 2; nb++)
        #pragma unroll
        for (int sub = 0; sub < 2; sub++) {
            const int j  = nb * 2 + sub;
            const int hc = wid * 32 + nb * 16 + sub * 8 + c2;
            #pragma unroll
            for (int o = 0; o < OUTD; o++) {
                float2 wv = *(const float2*)&Wout[(size_t)o * HID + H0 + hc];
                pr0[o] = fmaf(rmv[j].x,     wv.x, fmaf(rmv[j].y,     wv.y, pr0[o]));
                pr1[o] = fmaf(rmv[4 + j].x, wv.x, fmaf(rmv[4 + j].y, wv.y, pr1[o]));
            }
        }
    #pragma unroll
    for (int o = 0; o < OUTD; o++) {
        pr0[o] += __shfl_xor_sync(0xffffffffu, pr0[o], 1);
        pr0[o] += __shfl_xor_sync(0xffffffffu, pr0[o], 2);
        pr1[o] += __shfl_xor_sync(0xffffffffu, pr1[o], 1);
        pr1[o] += __shfl_xor_sync(0xffffffffu, pr1[o], 2);
    }
    __syncthreads();
    float* wred = (float*)(smraw + L_OFF_UPART);
    if ((lane & 3) == 0) {
        #pragma unroll
        for (int o = 0; o < OUTD; o++) {
            wred[(wid * 16 + r)     * 12 + o] = pr0[o];
            wred[(wid * 16 + r + 8) * 12 + o] = pr1[o];
        }
    }
    __syncthreads();
    if (tid < ROWS_PER_CL * OUTD) {
        int row = tid / OUTD;
        int o   = tid % OUTD;
        float s = 0.f;
        #pragma unroll
        for (int w = 0; w < 8; w++) s += wred[(w * 16 + row) * 12 + o];
        atomicAdd(&g_logits[(b0 + row) * OUTD + o], s);
    }
    cl.sync();
}

// ---------------- softmax kernel ----------------
__global__ __launch_bounds__(BATCH) void softmax_kernel(float* __restrict__ out) {
    const int b = threadIdx.x;
    float v[OUTD];
    #pragma unroll
    for (int o = 0; o < OUTD; o++) v[o] = g_logits[b * OUTD + o];
    float mx = v[0];
    #pragma unroll
    for (int o = 1; o < OUTD; o++) mx = fmaxf(mx, v[o]);
    float e[OUTD], sum = 0.0f;
    #pragma unroll
    for (int o = 0; o < OUTD; o++) { e[o] = expf(v[o] - mx); sum += e[o]; }
    float inv = 1.0f / sum;
    #pragma unroll
    for (int o = 0; o < OUTD; o++) out[b * OUTD + o] = e[o] * inv;
}

// ---------------- launch: loop FIRST (claims 64 SMs), then gemm fills the rest ----------------
extern "C" void kernel_launch(void* const* d_in, const int* in_sizes, int n_in,
                              void* d_out, int out_size) {
    const float* spk  = (const float*)d_in[0];
    const float* Win  = (const float*)d_in[1];
    const float* Wout = (const float*)d_in[2];
    const float* pin  = (const float*)d_in[3];
    const float* pout = (const float*)d_in[4];
    const float* l    = (const float*)d_in[5];
    float* out = (float*)d_out;

    static cudaStream_t sG = nullptr;
    static cudaEvent_t evPrep = nullptr, evLoop = nullptr, evGemm = nullptr;
    if (!sG) {
        cudaStreamCreateWithFlags(&sG, cudaStreamNonBlocking);
        cudaEventCreateWithFlags(&evPrep, cudaEventDisableTiming);
        cudaEventCreateWithFlags(&evLoop, cudaEventDisableTiming);
        cudaEventCreateWithFlags(&evGemm, cudaEventDisableTiming);
        cudaFuncSetAttribute(loop_kernel, cudaFuncAttributeMaxDynamicSharedMemorySize, LOOP_SMEM_PAD);
        cudaFuncSetAttribute(gemm_kernel, cudaFuncAttributeMaxDynamicSharedMemorySize, GEMM_SMEM);
    }

    prep_kernel<<<PREP_BLKS, 256>>>(spk, Win);
    cudaEventRecord(evPrep, 0);
    cudaStreamWaitEvent(sG, evPrep, 0);

    // loop first (default stream) -> placed on empty GPU, 1 CTA/SM on 64 SMs
    loop_kernel<<<NCTAS_LOOP, 256, LOOP_SMEM_PAD>>>(pin, pout, l, Wout);
    // gemm second (stream sG) -> fills the remaining 84 SMs at 2 CTAs/SM
    gemm_kernel<<<NCTAS_GEMM, 256, GEMM_SMEM, sG>>>();

    cudaEventRecord(evGemm, sG);
    cudaStreamWaitEvent(0, evGemm, 0);
    softmax_kernel<<<1, BATCH>>>(out);
}